// round 4
// baseline (speedup 1.0000x reference)
#include <cuda_runtime.h>

// Packed fp32x2 helpers (SASS FFMA2 path — PTX-only, sm_100+)
#define PACK2(d, s)       asm("mov.b64 %0, {%1, %1};" : "=l"(d) : "f"(s))
#define UNPACK2(lo, hi, s) asm("mov.b64 {%0, %1}, %2;" : "=f"(lo), "=f"(hi) : "l"(s))
#define FMA2(d, a, b)     asm("fma.rn.f32x2 %0, %1, %2, %0;" : "+l"(d) : "l"(a), "l"(b))

typedef unsigned long long u64;

// Shared memory layout (in floats):
//   [0,2048)      XT[64][32]          X transposed (k-major)
//   [2048,18432)  Wall[64][256]       Wq|Wk|Wv|Wr concatenated (phase A only)
//     aliased after phase A:
//       sc at 2048 : [2][32][36] scores (pad 36)
//       at at 4352 : [2][32][33] attn   (pad 33)
//   [18432,20544) qs [2][32][33]      Q (pad 33)
//   [20544,22848) kT [2][32][36]      K transposed: kT[h][a][g] (pad 36)
//   [22848,24896) vs [2][32][32]      V natural
//   [24896,27072) res[32][68]         X@Wr (pad 68)
// total = 27072 floats = 108288 bytes -> 2 CTAs/SM

__global__ void __launch_bounds__(256, 2)
interact_kernel(const float* __restrict__ X,
                const float* __restrict__ Wq,
                const float* __restrict__ Wk,
                const float* __restrict__ Wv,
                const float* __restrict__ Wr,
                float* __restrict__ Out)
{
    extern __shared__ float sm[];
    float* XT   = sm;
    float* Wall = sm + 2048;
    float* sc   = sm + 2048;    // alias (Wall dead after phase A)
    float* at   = sm + 4352;    // alias
    float* qs   = sm + 18432;
    float* kT   = sm + 20544;
    float* vs   = sm + 22848;
    float* res  = sm + 24896;

    const int tid  = threadIdx.x;
    const int lane = tid & 31;
    const int warp = tid >> 5;
    const long b   = blockIdx.x;

    // ---- load X transposed: lane=f, warp picks 8 d's (conflict-free STS) ----
    {
        const float* Xb = X + b * 2048;
        const int f = lane, d0 = warp * 8;
        float4 x0 = *(const float4*)(Xb + f * 64 + d0);
        float4 x1 = *(const float4*)(Xb + f * 64 + d0 + 4);
        XT[(d0+0)*32+f]=x0.x; XT[(d0+1)*32+f]=x0.y;
        XT[(d0+2)*32+f]=x0.z; XT[(d0+3)*32+f]=x0.w;
        XT[(d0+4)*32+f]=x1.x; XT[(d0+5)*32+f]=x1.y;
        XT[(d0+6)*32+f]=x1.z; XT[(d0+7)*32+f]=x1.w;
    }
    // ---- load Wall[64][256] = Wq|Wk|Wv|Wr (coalesced) ----
    {
        const int m  = (tid & 63) >> 4;             // which weight matrix (fixed per thread)
        const int e4 = tid & 15;                    // float4 col within matrix
        const float* Wsrc = (m == 0) ? Wq : (m == 1) ? Wk : (m == 2) ? Wv : Wr;
        #pragma unroll
        for (int t = 0; t < 16; t++) {
            int f4 = tid + 256 * t;                 // global float4 index
            int k  = f4 >> 6;                       // row
            float4 w = *(const float4*)(Wsrc + k * 64 + e4 * 4);
            *(float4*)(Wall + f4 * 4) = w;
        }
    }
    __syncthreads();

    // ---- phase A: [32x64] @ [64x256] -> Q,K,V,Res   (FFMA2, 8x4 tiles) ----
    {
        const int rt = tid >> 6;          // 0..3  -> rows f0..f0+7
        const int ct = tid & 63;          // 0..63 -> cols c0..c0+3
        const int f0 = rt * 8;
        const int c0 = ct * 4;
        u64 acc[4][4];
        #pragma unroll
        for (int j = 0; j < 4; j++)
            #pragma unroll
            for (int cc = 0; cc < 4; cc++) acc[j][cc] = 0ULL;

        #pragma unroll 4
        for (int k = 0; k < 64; k++) {
            const ulonglong2* xt2 = (const ulonglong2*)(XT + k * 32);
            ulonglong2 xa = xt2[rt * 2];        // pairs (f0,f0+1),(f0+2,f0+3) - broadcast
            ulonglong2 xb = xt2[rt * 2 + 1];    // pairs (f0+4,f0+5),(f0+6,f0+7)
            float4 w4 = *(const float4*)(Wall + k * 256 + c0);
            u64 wp0, wp1, wp2, wp3;
            PACK2(wp0, w4.x); PACK2(wp1, w4.y); PACK2(wp2, w4.z); PACK2(wp3, w4.w);
            FMA2(acc[0][0], xa.x, wp0); FMA2(acc[0][1], xa.x, wp1);
            FMA2(acc[0][2], xa.x, wp2); FMA2(acc[0][3], xa.x, wp3);
            FMA2(acc[1][0], xa.y, wp0); FMA2(acc[1][1], xa.y, wp1);
            FMA2(acc[1][2], xa.y, wp2); FMA2(acc[1][3], xa.y, wp3);
            FMA2(acc[2][0], xb.x, wp0); FMA2(acc[2][1], xb.x, wp1);
            FMA2(acc[2][2], xb.x, wp2); FMA2(acc[2][3], xb.x, wp3);
            FMA2(acc[3][0], xb.y, wp0); FMA2(acc[3][1], xb.y, wp1);
            FMA2(acc[3][2], xb.y, wp2); FMA2(acc[3][3], xb.y, wp3);
        }
        #pragma unroll
        for (int j = 0; j < 4; j++) {
            #pragma unroll
            for (int cc = 0; cc < 4; cc++) {
                float lo, hi;
                UNPACK2(lo, hi, acc[j][cc]);
                const int c  = c0 + cc;
                const int fA = f0 + 2 * j, fBr = fA + 1;
                if (c < 64) {                      // Q
                    int h = c >> 5, a = c & 31;
                    qs[(h*32+fA)*33 + a] = lo;
                    qs[(h*32+fBr)*33 + a] = hi;
                } else if (c < 128) {              // K (store transposed: [h][a][g])
                    int e = c - 64, h = e >> 5, a = e & 31;
                    kT[(h*32+a)*36 + fA] = lo;
                    kT[(h*32+a)*36 + fBr] = hi;
                } else if (c < 192) {              // V
                    int e = c - 128, h = e >> 5, a = e & 31;
                    vs[(h*32+fA)*32 + a] = lo;
                    vs[(h*32+fBr)*32 + a] = hi;
                } else {                           // Res
                    int e = c - 192;
                    res[fA*68 + e] = lo;
                    res[fBr*68 + e] = hi;
                }
            }
        }
    }
    __syncthreads();

    // ---- phase B: scores[h][f][g] = sum_a Q[h][f][a] * K[h][g][a] ----
    const int h    = tid >> 7;          // head
    const int t    = tid & 127;
    const int fr   = t >> 2;            // f row (0..31)
    const int seg8 = (t & 3) * 8;       // 8-wide col segment
    {
        u64 accb[4] = {0ULL,0ULL,0ULL,0ULL};
        #pragma unroll 8
        for (int a = 0; a < 32; a++) {
            float qv = qs[(h*32+fr)*33 + a];
            u64 qp; PACK2(qp, qv);
            const ulonglong2* kr = (const ulonglong2*)(kT + (h*32+a)*36 + seg8);
            ulonglong2 k01 = kr[0], k23 = kr[1];
            FMA2(accb[0], qp, k01.x); FMA2(accb[1], qp, k01.y);
            FMA2(accb[2], qp, k23.x); FMA2(accb[3], qp, k23.y);
        }
        float s0,s1,s2,s3,s4,s5,s6,s7;
        UNPACK2(s0, s1, accb[0]); UNPACK2(s2, s3, accb[1]);
        UNPACK2(s4, s5, accb[2]); UNPACK2(s6, s7, accb[3]);
        float* dst = sc + (h*32+fr)*36 + seg8;
        *(float4*)(dst)     = make_float4(s0, s1, s2, s3);
        *(float4*)(dst + 4) = make_float4(s4, s5, s6, s7);
    }
    __syncthreads();

    // ---- phase C: softmax over g (one warp = 8 rows, lane = g) ----
    {
        #pragma unroll
        for (int i = 0; i < 8; i++) {
            int r = warp * 8 + i;                 // r = h*32+f
            float x = sc[r*36 + lane];
            float m = x;
            #pragma unroll
            for (int o = 16; o > 0; o >>= 1)
                m = fmaxf(m, __shfl_xor_sync(0xffffffffu, m, o));
            float e = __expf(x - m);
            float ssum = e;
            #pragma unroll
            for (int o = 16; o > 0; o >>= 1)
                ssum += __shfl_xor_sync(0xffffffffu, ssum, o);
            at[r*33 + lane] = __fdividef(e, ssum);
        }
    }
    __syncthreads();

    // ---- phase D: out = attn @ V + res, relu, store ----
    {
        u64 accd[4] = {0ULL,0ULL,0ULL,0ULL};
        #pragma unroll 8
        for (int g = 0; g < 32; g++) {
            float av = at[(h*32+fr)*33 + g];
            u64 ap; PACK2(ap, av);
            const ulonglong2* vr = (const ulonglong2*)(vs + (h*32+g)*32 + seg8);
            ulonglong2 v01 = vr[0], v23 = vr[1];
            FMA2(accd[0], ap, v01.x); FMA2(accd[1], ap, v01.y);
            FMA2(accd[2], ap, v23.x); FMA2(accd[3], ap, v23.y);
        }
        float o0,o1,o2,o3,o4,o5,o6,o7;
        UNPACK2(o0, o1, accd[0]); UNPACK2(o2, o3, accd[1]);
        UNPACK2(o4, o5, accd[2]); UNPACK2(o6, o7, accd[3]);
        const int e0 = h * 32 + seg8;
        const float4 r0 = *(const float4*)(res + fr*68 + e0);
        const float4 r1 = *(const float4*)(res + fr*68 + e0 + 4);
        o0 += r0.x; o1 += r0.y; o2 += r0.z; o3 += r0.w;
        o4 += r1.x; o5 += r1.y; o6 += r1.z; o7 += r1.w;
        o0 = fmaxf(o0, 0.f); o1 = fmaxf(o1, 0.f); o2 = fmaxf(o2, 0.f); o3 = fmaxf(o3, 0.f);
        o4 = fmaxf(o4, 0.f); o5 = fmaxf(o5, 0.f); o6 = fmaxf(o6, 0.f); o7 = fmaxf(o7, 0.f);
        float* outp = Out + b * 2048 + fr * 64 + e0;
        *(float4*)(outp)     = make_float4(o0, o1, o2, o3);
        *(float4*)(outp + 4) = make_float4(o4, o5, o6, o7);
    }
}

extern "C" void kernel_launch(void* const* d_in, const int* in_sizes, int n_in,
                              void* d_out, int out_size)
{
    const float* X  = (const float*)d_in[0];
    const float* Wq = (const float*)d_in[1];
    const float* Wk = (const float*)d_in[2];
    const float* Wv = (const float*)d_in[3];
    const float* Wr = (const float*)d_in[4];
    float* Out = (float*)d_out;

    const int nb = in_sizes[0] / 2048;          // 16384 batches
    const size_t smem = 27072 * sizeof(float);  // 108288 B

    cudaFuncSetAttribute(interact_kernel,
                         cudaFuncAttributeMaxDynamicSharedMemorySize, (int)smem);
    interact_kernel<<<nb, 256, smem>>>(X, Wq, Wk, Wv, Wr, Out);
}

// round 5
// speedup vs baseline: 1.0387x; 1.0387x over previous
#include <cuda_runtime.h>

// Packed fp32x2 helpers (SASS FFMA2 path — PTX-only, sm_100+)
#define PACK2(d, s)        asm("mov.b64 %0, {%1, %1};" : "=l"(d) : "f"(s))
#define UNPACK2(lo, hi, s) asm("mov.b64 {%0, %1}, %2;" : "=f"(lo), "=f"(hi) : "l"(s))
#define FMA2(d, a, b)      asm("fma.rn.f32x2 %0, %1, %2, %0;" : "+l"(d) : "l"(a), "l"(b))

typedef unsigned long long u64;

// Shared memory layout (floats):
//   [0,2048)       XT[64][32]         X transposed (k-major)
//   [2048,18432)   Wall[64][256]      Wq|Wk|Wv|Wr concat (phase A only)
//     aliased after phase A:
//       sc  @2048 : [2][32][36]       scores (pad 36)
//       atT @4352 : [2][32][34]       attn TRANSPOSED: atT[h][g][f] (pad 34)
//   [18432,20608)  qsT[2][32][34]     Q TRANSPOSED: qsT[h][a][f] (pad 34)
//   [20608,22912)  kT [2][32][36]     K transposed: kT[h][a][g] (pad 36)
//   [22912,24960)  vs [2][32][32]     V natural: vs[h][g][e]
//   [24960,27136)  res[32][68]        X@Wr (pad 68)
// total 27136 floats = 108544 B -> 2 CTAs/SM

__global__ void __launch_bounds__(256, 2)
interact_kernel(const float* __restrict__ X,
                const float* __restrict__ Wq,
                const float* __restrict__ Wk,
                const float* __restrict__ Wv,
                const float* __restrict__ Wr,
                float* __restrict__ Out)
{
    extern __shared__ float sm[];
    float* XT   = sm;
    float* Wall = sm + 2048;
    float* sc   = sm + 2048;    // alias (Wall dead after phase A)
    float* atT  = sm + 4352;    // alias
    float* qsT  = sm + 18432;
    float* kT   = sm + 20608;
    float* vs   = sm + 22912;
    float* res  = sm + 24960;

    const int tid  = threadIdx.x;
    const int lane = tid & 31;
    const int warp = tid >> 5;
    const long b   = blockIdx.x;

    // ---- load X transposed: lane=f, warp picks 8 d's (conflict-free STS) ----
    {
        const float* Xb = X + b * 2048;
        const int f = lane, d0 = warp * 8;
        float4 x0 = *(const float4*)(Xb + f * 64 + d0);
        float4 x1 = *(const float4*)(Xb + f * 64 + d0 + 4);
        XT[(d0+0)*32+f]=x0.x; XT[(d0+1)*32+f]=x0.y;
        XT[(d0+2)*32+f]=x0.z; XT[(d0+3)*32+f]=x0.w;
        XT[(d0+4)*32+f]=x1.x; XT[(d0+5)*32+f]=x1.y;
        XT[(d0+6)*32+f]=x1.z; XT[(d0+7)*32+f]=x1.w;
    }
    // ---- load Wall[64][256] = Wq|Wk|Wv|Wr (coalesced) ----
    {
        const int m  = (tid & 63) >> 4;
        const int e4 = tid & 15;
        const float* Wsrc = (m == 0) ? Wq : (m == 1) ? Wk : (m == 2) ? Wv : Wr;
        #pragma unroll
        for (int t = 0; t < 16; t++) {
            int f4 = tid + 256 * t;
            int k  = f4 >> 6;
            float4 w = *(const float4*)(Wsrc + k * 64 + e4 * 4);
            *(float4*)(Wall + f4 * 4) = w;
        }
    }
    __syncthreads();

    // ---- phase A: [32x64] @ [64x256] -> Q,K,V,Res   (FFMA2, 8x4 tiles) ----
    // Lane map tuned for smem wavefronts: rows vary within quad (4 distinct
    // broadcast addrs), cols shared by 4 lanes (8 distinct 16B addrs -> 1 wf).
    {
        const int rt = lane & 3;                       // row tile 0..3
        const int f0 = rt * 8;
        const int c0 = (warp * 8 + (lane >> 2)) * 4;   // column base (0..252)
        u64 acc[4][4];
        #pragma unroll
        for (int j = 0; j < 4; j++)
            #pragma unroll
            for (int cc = 0; cc < 4; cc++) acc[j][cc] = 0ULL;

        #pragma unroll 4
        for (int k = 0; k < 64; k++) {
            const ulonglong2* xt2 = (const ulonglong2*)(XT + k * 32);
            ulonglong2 xa = xt2[rt * 2];        // pairs (f0,f0+1),(f0+2,f0+3)
            ulonglong2 xb = xt2[rt * 2 + 1];    // pairs (f0+4,f0+5),(f0+6,f0+7)
            float4 w4 = *(const float4*)(Wall + k * 256 + c0);
            u64 wp0, wp1, wp2, wp3;
            PACK2(wp0, w4.x); PACK2(wp1, w4.y); PACK2(wp2, w4.z); PACK2(wp3, w4.w);
            FMA2(acc[0][0], xa.x, wp0); FMA2(acc[0][1], xa.x, wp1);
            FMA2(acc[0][2], xa.x, wp2); FMA2(acc[0][3], xa.x, wp3);
            FMA2(acc[1][0], xa.y, wp0); FMA2(acc[1][1], xa.y, wp1);
            FMA2(acc[1][2], xa.y, wp2); FMA2(acc[1][3], xa.y, wp3);
            FMA2(acc[2][0], xb.x, wp0); FMA2(acc[2][1], xb.x, wp1);
            FMA2(acc[2][2], xb.x, wp2); FMA2(acc[2][3], xb.x, wp3);
            FMA2(acc[3][0], xb.y, wp0); FMA2(acc[3][1], xb.y, wp1);
            FMA2(acc[3][2], xb.y, wp2); FMA2(acc[3][3], xb.y, wp3);
        }
        // Epilogue: branch is warp-uniform (each warp covers 32 consecutive cols)
        #pragma unroll
        for (int j = 0; j < 4; j++) {
            #pragma unroll
            for (int cc = 0; cc < 4; cc++) {
                float lo, hi;
                UNPACK2(lo, hi, acc[j][cc]);
                const int c  = c0 + cc;
                const int fA = f0 + 2 * j;     // even -> 8B-aligned float2 slots
                if (c < 64) {                  // Q -> transposed qsT[h][a][f]
                    int h = c >> 5, a = c & 31;
                    *(float2*)(qsT + (h*32+a)*34 + fA) = make_float2(lo, hi);
                } else if (c < 128) {          // K -> transposed kT[h][a][g]
                    int e = c - 64, h = e >> 5, a = e & 31;
                    *(float2*)(kT + (h*32+a)*36 + fA) = make_float2(lo, hi);
                } else if (c < 192) {          // V natural vs[h][f][a]
                    int e = c - 128, h = e >> 5, a = e & 31;
                    vs[(h*32+fA)*32 + a]   = lo;
                    vs[(h*32+fA+1)*32 + a] = hi;
                } else {                       // Res natural
                    int e = c - 192;
                    res[fA*68 + e]     = lo;
                    res[(fA+1)*68 + e] = hi;
                }
            }
        }
    }
    __syncthreads();

    // ---- phase B: scores[h][f][g] = sum_a Q[h][f][a]*K[h][g][a] ----
    // 2 rows x 4 cols per thread; A-operand = native LDS.64 row-pair from qsT,
    // B-operand LDS.128 shared by 8 lanes -> 2 wavefronts/warp/iter.
    const int h   = tid >> 7;
    const int t   = tid & 127;
    const int fr0 = (t >> 3) * 2;       // even row pair base
    const int c0b = (t & 7) * 4;        // 4-wide col segment
    {
        u64 accb[4] = {0ULL,0ULL,0ULL,0ULL};
        #pragma unroll 8
        for (int a = 0; a < 32; a++) {
            u64 q2 = *(const u64*)(qsT + (h*32+a)*34 + fr0);   // (f,f+1) pair
            float4 kv = *(const float4*)(kT + (h*32+a)*36 + c0b);
            u64 k0, k1, k2, k3;
            PACK2(k0, kv.x); PACK2(k1, kv.y); PACK2(k2, kv.z); PACK2(k3, kv.w);
            FMA2(accb[0], q2, k0); FMA2(accb[1], q2, k1);
            FMA2(accb[2], q2, k2); FMA2(accb[3], q2, k3);
        }
        float a0,b0,a1,b1,a2,b2,a3,b3;
        UNPACK2(a0, b0, accb[0]); UNPACK2(a1, b1, accb[1]);
        UNPACK2(a2, b2, accb[2]); UNPACK2(a3, b3, accb[3]);
        *(float4*)(sc + (h*32+fr0  )*36 + c0b) = make_float4(a0, a1, a2, a3);
        *(float4*)(sc + (h*32+fr0+1)*36 + c0b) = make_float4(b0, b1, b2, b3);
    }
    __syncthreads();

    // ---- phase C: softmax over g (one warp = 8 rows, lane = g) ----
    {
        #pragma unroll
        for (int i = 0; i < 8; i++) {
            int r  = warp * 8 + i;            // r = h*32 + f
            int hh = r >> 5, f = r & 31;
            float x = sc[r*36 + lane];
            float m = x;
            #pragma unroll
            for (int o = 16; o > 0; o >>= 1)
                m = fmaxf(m, __shfl_xor_sync(0xffffffffu, m, o));
            float e = __expf(x - m);
            float ssum = e;
            #pragma unroll
            for (int o = 16; o > 0; o >>= 1)
                ssum += __shfl_xor_sync(0xffffffffu, ssum, o);
            atT[(hh*32+lane)*34 + f] = __fdividef(e, ssum);  // transposed store
        }
    }
    __syncthreads();

    // ---- phase D: out = attn @ V + res, relu, store ----
    {
        u64 accd[4] = {0ULL,0ULL,0ULL,0ULL};
        #pragma unroll 8
        for (int g = 0; g < 32; g++) {
            u64 a2 = *(const u64*)(atT + (h*32+g)*34 + fr0);   // (f,f+1) pair
            float4 vv = *(const float4*)(vs + (h*32+g)*32 + c0b);
            u64 v0, v1, v2, v3;
            PACK2(v0, vv.x); PACK2(v1, vv.y); PACK2(v2, vv.z); PACK2(v3, vv.w);
            FMA2(accd[0], a2, v0); FMA2(accd[1], a2, v1);
            FMA2(accd[2], a2, v2); FMA2(accd[3], a2, v3);
        }
        float a0,b0,a1,b1,a2,b2,a3,b3;
        UNPACK2(a0, b0, accd[0]); UNPACK2(a1, b1, accd[1]);
        UNPACK2(a2, b2, accd[2]); UNPACK2(a3, b3, accd[3]);

        const int e0 = h * 32 + c0b;
        const float4 r0 = *(const float4*)(res + fr0*68 + e0);
        const float4 r1 = *(const float4*)(res + (fr0+1)*68 + e0);
        a0 = fmaxf(a0 + r0.x, 0.f); a1 = fmaxf(a1 + r0.y, 0.f);
        a2 = fmaxf(a2 + r0.z, 0.f); a3 = fmaxf(a3 + r0.w, 0.f);
        b0 = fmaxf(b0 + r1.x, 0.f); b1 = fmaxf(b1 + r1.y, 0.f);
        b2 = fmaxf(b2 + r1.z, 0.f); b3 = fmaxf(b3 + r1.w, 0.f);

        float* outp = Out + b * 2048 + fr0 * 64 + e0;
        *(float4*)(outp)      = make_float4(a0, a1, a2, a3);
        *(float4*)(outp + 64) = make_float4(b0, b1, b2, b3);
    }
}

extern "C" void kernel_launch(void* const* d_in, const int* in_sizes, int n_in,
                              void* d_out, int out_size)
{
    const float* X  = (const float*)d_in[0];
    const float* Wq = (const float*)d_in[1];
    const float* Wk = (const float*)d_in[2];
    const float* Wv = (const float*)d_in[3];
    const float* Wr = (const float*)d_in[4];
    float* Out = (float*)d_out;

    const int nb = in_sizes[0] / 2048;          // 16384 batches
    const size_t smem = 27136 * sizeof(float);  // 108544 B

    cudaFuncSetAttribute(interact_kernel,
                         cudaFuncAttributeMaxDynamicSharedMemorySize, (int)smem);
    interact_kernel<<<nb, 256, smem>>>(X, Wq, Wk, Wv, Wr, Out);
}

// round 6
// speedup vs baseline: 1.0943x; 1.0535x over previous
#include <cuda_runtime.h>

// Packed fp32x2 helpers (SASS FFMA2 path — PTX-only, sm_100+)
#define PACK2(d, s)        asm("mov.b64 %0, {%1, %1};" : "=l"(d) : "f"(s))
#define UNPACK2(lo, hi, s) asm("mov.b64 {%0, %1}, %2;" : "=f"(lo), "=f"(hi) : "l"(s))
#define FMA2(d, a, b)      asm("fma.rn.f32x2 %0, %1, %2, %0;" : "+l"(d) : "l"(a), "l"(b))

typedef unsigned long long u64;

// Shared memory layout (floats):
//   [0,2048)       XT[64][32]         X transposed (k-major)
//   [2048,18432)   Wall[64][256]      Wq|Wk|Wv|Wr concat (phase A only)
//     aliased after phase A:
//       sc  @2048 : [2][32][36]       scores (pad 36)
//       atT @4352 : [2][32][34]       attn TRANSPOSED: atT[h][g][f] (pad 34)
//   [18432,20608)  qsT[2][32][34]     Q TRANSPOSED: qsT[h][a][f] (pad 34)
//   [20608,22912)  kT [2][32][36]     K transposed: kT[h][a][g] (pad 36)
//   [22912,24960)  vs [2][32][32]     V natural: vs[h][g][e]
//   [24960,27136)  res[32][68]        X@Wr (pad 68)
// total 27136 floats = 108544 B -> 2 CTAs/SM

__global__ void __launch_bounds__(256, 2)
interact_kernel(const float* __restrict__ X,
                const float* __restrict__ Wq,
                const float* __restrict__ Wk,
                const float* __restrict__ Wv,
                const float* __restrict__ Wr,
                float* __restrict__ Out)
{
    extern __shared__ float sm[];
    float* XT   = sm;
    float* Wall = sm + 2048;
    float* sc   = sm + 2048;    // alias (Wall dead after phase A)
    float* atT  = sm + 4352;    // alias
    float* qsT  = sm + 18432;
    float* kT   = sm + 20608;
    float* vs   = sm + 22912;
    float* res  = sm + 24960;

    const int tid  = threadIdx.x;
    const int lane = tid & 31;
    const int warp = tid >> 5;
    const long b   = blockIdx.x;

    // ---- load X transposed: lane=f, warp picks 8 d's (conflict-free STS) ----
    {
        const float* Xb = X + b * 2048;
        const int f = lane, d0 = warp * 8;
        float4 x0 = *(const float4*)(Xb + f * 64 + d0);
        float4 x1 = *(const float4*)(Xb + f * 64 + d0 + 4);
        XT[(d0+0)*32+f]=x0.x; XT[(d0+1)*32+f]=x0.y;
        XT[(d0+2)*32+f]=x0.z; XT[(d0+3)*32+f]=x0.w;
        XT[(d0+4)*32+f]=x1.x; XT[(d0+5)*32+f]=x1.y;
        XT[(d0+6)*32+f]=x1.z; XT[(d0+7)*32+f]=x1.w;
    }
    // ---- load Wall[64][256] = Wq|Wk|Wv|Wr (coalesced) ----
    {
        const int m  = (tid & 63) >> 4;
        const int e4 = tid & 15;
        const float* Wsrc = (m == 0) ? Wq : (m == 1) ? Wk : (m == 2) ? Wv : Wr;
        #pragma unroll
        for (int t = 0; t < 16; t++) {
            int f4 = tid + 256 * t;
            int k  = f4 >> 6;
            float4 w = *(const float4*)(Wsrc + k * 64 + e4 * 4);
            *(float4*)(Wall + f4 * 4) = w;
        }
    }
    __syncthreads();

    // ---- phase A: [32x64] @ [64x256] -> Q,K,V,Res   (FFMA2, 8x4 tiles) ----
    // Lane map tuned for smem wavefronts: rows vary within quad (4 distinct
    // broadcast addrs), cols shared by 4 lanes (8 distinct 16B addrs -> 1 wf).
    {
        const int rt = lane & 3;                       // row tile 0..3
        const int f0 = rt * 8;
        const int c0 = (warp * 8 + (lane >> 2)) * 4;   // column base (0..252)
        u64 acc[4][4];
        #pragma unroll
        for (int j = 0; j < 4; j++)
            #pragma unroll
            for (int cc = 0; cc < 4; cc++) acc[j][cc] = 0ULL;

        #pragma unroll 4
        for (int k = 0; k < 64; k++) {
            const ulonglong2* xt2 = (const ulonglong2*)(XT + k * 32);
            ulonglong2 xa = xt2[rt * 2];        // pairs (f0,f0+1),(f0+2,f0+3)
            ulonglong2 xb = xt2[rt * 2 + 1];    // pairs (f0+4,f0+5),(f0+6,f0+7)
            float4 w4 = *(const float4*)(Wall + k * 256 + c0);
            u64 wp0, wp1, wp2, wp3;
            PACK2(wp0, w4.x); PACK2(wp1, w4.y); PACK2(wp2, w4.z); PACK2(wp3, w4.w);
            FMA2(acc[0][0], xa.x, wp0); FMA2(acc[0][1], xa.x, wp1);
            FMA2(acc[0][2], xa.x, wp2); FMA2(acc[0][3], xa.x, wp3);
            FMA2(acc[1][0], xa.y, wp0); FMA2(acc[1][1], xa.y, wp1);
            FMA2(acc[1][2], xa.y, wp2); FMA2(acc[1][3], xa.y, wp3);
            FMA2(acc[2][0], xb.x, wp0); FMA2(acc[2][1], xb.x, wp1);
            FMA2(acc[2][2], xb.x, wp2); FMA2(acc[2][3], xb.x, wp3);
            FMA2(acc[3][0], xb.y, wp0); FMA2(acc[3][1], xb.y, wp1);
            FMA2(acc[3][2], xb.y, wp2); FMA2(acc[3][3], xb.y, wp3);
        }
        // Epilogue: branch is warp-uniform (each warp covers 32 consecutive cols)
        #pragma unroll
        for (int j = 0; j < 4; j++) {
            #pragma unroll
            for (int cc = 0; cc < 4; cc++) {
                float lo, hi;
                UNPACK2(lo, hi, acc[j][cc]);
                const int c  = c0 + cc;
                const int fA = f0 + 2 * j;     // even -> 8B-aligned float2 slots
                if (c < 64) {                  // Q -> transposed qsT[h][a][f]
                    int h = c >> 5, a = c & 31;
                    *(float2*)(qsT + (h*32+a)*34 + fA) = make_float2(lo, hi);
                } else if (c < 128) {          // K -> transposed kT[h][a][g]
                    int e = c - 64, h = e >> 5, a = e & 31;
                    *(float2*)(kT + (h*32+a)*36 + fA) = make_float2(lo, hi);
                } else if (c < 192) {          // V natural vs[h][f][a]
                    int e = c - 128, h = e >> 5, a = e & 31;
                    vs[(h*32+fA)*32 + a]   = lo;
                    vs[(h*32+fA+1)*32 + a] = hi;
                } else {                       // Res natural
                    int e = c - 192;
                    res[fA*68 + e]     = lo;
                    res[(fA+1)*68 + e] = hi;
                }
            }
        }
    }
    __syncthreads();

    // ---- phase B: scores[h][f][g] = sum_a Q[h][f][a]*K[h][g][a] ----
    // 2 rows x 4 cols per thread; A-operand = native LDS.64 row-pair from qsT,
    // B-operand LDS.128 shared by 8 lanes -> 2 wavefronts/warp/iter.
    const int h   = tid >> 7;
    const int t   = tid & 127;
    const int fr0 = (t >> 3) * 2;       // even row pair base
    const int c0b = (t & 7) * 4;        // 4-wide col segment
    {
        u64 accb[4] = {0ULL,0ULL,0ULL,0ULL};
        #pragma unroll 8
        for (int a = 0; a < 32; a++) {
            u64 q2 = *(const u64*)(qsT + (h*32+a)*34 + fr0);   // (f,f+1) pair
            float4 kv = *(const float4*)(kT + (h*32+a)*36 + c0b);
            u64 k0, k1, k2, k3;
            PACK2(k0, kv.x); PACK2(k1, kv.y); PACK2(k2, kv.z); PACK2(k3, kv.w);
            FMA2(accb[0], q2, k0); FMA2(accb[1], q2, k1);
            FMA2(accb[2], q2, k2); FMA2(accb[3], q2, k3);
        }
        float a0,b0,a1,b1,a2,b2,a3,b3;
        UNPACK2(a0, b0, accb[0]); UNPACK2(a1, b1, accb[1]);
        UNPACK2(a2, b2, accb[2]); UNPACK2(a3, b3, accb[3]);
        *(float4*)(sc + (h*32+fr0  )*36 + c0b) = make_float4(a0, a1, a2, a3);
        *(float4*)(sc + (h*32+fr0+1)*36 + c0b) = make_float4(b0, b1, b2, b3);
    }
    __syncthreads();

    // ---- phase C: softmax over g (one warp = 8 rows, lane = g) ----
    {
        #pragma unroll
        for (int i = 0; i < 8; i++) {
            int r  = warp * 8 + i;            // r = h*32 + f
            int hh = r >> 5, f = r & 31;
            float x = sc[r*36 + lane];
            float m = x;
            #pragma unroll
            for (int o = 16; o > 0; o >>= 1)
                m = fmaxf(m, __shfl_xor_sync(0xffffffffu, m, o));
            float e = __expf(x - m);
            float ssum = e;
            #pragma unroll
            for (int o = 16; o > 0; o >>= 1)
                ssum += __shfl_xor_sync(0xffffffffu, ssum, o);
            atT[(hh*32+lane)*34 + f] = __fdividef(e, ssum);  // transposed store
        }
    }
    __syncthreads();

    // ---- phase D: out = attn @ V + res, relu, store ----
    {
        u64 accd[4] = {0ULL,0ULL,0ULL,0ULL};
        #pragma unroll 8
        for (int g = 0; g < 32; g++) {
            u64 a2 = *(const u64*)(atT + (h*32+g)*34 + fr0);   // (f,f+1) pair
            float4 vv = *(const float4*)(vs + (h*32+g)*32 + c0b);
            u64 v0, v1, v2, v3;
            PACK2(v0, vv.x); PACK2(v1, vv.y); PACK2(v2, vv.z); PACK2(v3, vv.w);
            FMA2(accd[0], a2, v0); FMA2(accd[1], a2, v1);
            FMA2(accd[2], a2, v2); FMA2(accd[3], a2, v3);
        }
        float a0,b0,a1,b1,a2,b2,a3,b3;
        UNPACK2(a0, b0, accd[0]); UNPACK2(a1, b1, accd[1]);
        UNPACK2(a2, b2, accd[2]); UNPACK2(a3, b3, accd[3]);

        const int e0 = h * 32 + c0b;
        const float4 r0 = *(const float4*)(res + fr0*68 + e0);
        const float4 r1 = *(const float4*)(res + (fr0+1)*68 + e0);
        a0 = fmaxf(a0 + r0.x, 0.f); a1 = fmaxf(a1 + r0.y, 0.f);
        a2 = fmaxf(a2 + r0.z, 0.f); a3 = fmaxf(a3 + r0.w, 0.f);
        b0 = fmaxf(b0 + r1.x, 0.f); b1 = fmaxf(b1 + r1.y, 0.f);
        b2 = fmaxf(b2 + r1.z, 0.f); b3 = fmaxf(b3 + r1.w, 0.f);

        float* outp = Out + b * 2048 + fr0 * 64 + e0;
        *(float4*)(outp)      = make_float4(a0, a1, a2, a3);
        *(float4*)(outp + 64) = make_float4(b0, b1, b2, b3);
    }
}

extern "C" void kernel_launch(void* const* d_in, const int* in_sizes, int n_in,
                              void* d_out, int out_size)
{
    const float* X  = (const float*)d_in[0];
    const float* Wq = (const float*)d_in[1];
    const float* Wk = (const float*)d_in[2];
    const float* Wv = (const float*)d_in[3];
    const float* Wr = (const float*)d_in[4];
    float* Out = (float*)d_out;

    const int nb = in_sizes[0] / 2048;          // 16384 batches
    const size_t smem = 27136 * sizeof(float);  // 108544 B

    cudaFuncSetAttribute(interact_kernel,
                         cudaFuncAttributeMaxDynamicSharedMemorySize, (int)smem);
    interact_kernel<<<nb, 256, smem>>>(X, Wq, Wk, Wv, Wr, Out);
}

// round 7
// speedup vs baseline: 1.3160x; 1.2026x over previous
#include <cuda_runtime.h>

// Packed fp32x2 helpers (SASS FFMA2 path — PTX-only, sm_100+)
#define PACK2(d, s)        asm("mov.b64 %0, {%1, %1};" : "=l"(d) : "f"(s))
#define UNPACK2(lo, hi, s) asm("mov.b64 {%0, %1}, %2;" : "=f"(lo), "=f"(hi) : "l"(s))
#define FMA2(d, a, b)      asm("fma.rn.f32x2 %0, %1, %2, %0;" : "+l"(d) : "l"(a), "l"(b))

typedef unsigned long long u64;

// Shared memory layout (floats), 10880 floats = 43520 B -> 3 CTAs/SM:
//   [0,2176)      XT[64][32] (2048 used)   X transposed (k-major)
//                 aliased after phase A:
//                   atT[2][32][34]  attn TRANSPOSED: atT[h][g][f] (pad 34)
//   [2176,4352)   qsT[2][32][34]   Q TRANSPOSED: qsT[h][a][f] (pad 34)
//   [4352,6656)   kT [2][32][36]   K transposed: kT[h][a][g] (pad 36)
//   [6656,8704)   vs [2][32][32]   V natural: vs[h][g][e]
//   [8704,10880)  res[32][68]      X@Wr (pad 68)

__global__ void __launch_bounds__(256, 3)
interact_kernel(const float* __restrict__ X,
                const float* __restrict__ Wq,
                const float* __restrict__ Wk,
                const float* __restrict__ Wv,
                const float* __restrict__ Wr,
                float* __restrict__ Out)
{
    extern __shared__ float sm[];
    float* XT   = sm;          // phase A only
    float* atT  = sm;          // alias, written in fused B+C
    float* qsT  = sm + 2176;
    float* kT   = sm + 4352;
    float* vs   = sm + 6656;
    float* res  = sm + 8704;

    const int tid  = threadIdx.x;
    const int lane = tid & 31;
    const int warp = tid >> 5;
    const long b   = blockIdx.x;

    // ---- load X transposed: lane=f, warp picks 8 d's (conflict-free STS) ----
    {
        const float* Xb = X + b * 2048;
        const int f = lane, d0 = warp * 8;
        float4 x0 = *(const float4*)(Xb + f * 64 + d0);
        float4 x1 = *(const float4*)(Xb + f * 64 + d0 + 4);
        XT[(d0+0)*32+f]=x0.x; XT[(d0+1)*32+f]=x0.y;
        XT[(d0+2)*32+f]=x0.z; XT[(d0+3)*32+f]=x0.w;
        XT[(d0+4)*32+f]=x1.x; XT[(d0+5)*32+f]=x1.y;
        XT[(d0+6)*32+f]=x1.z; XT[(d0+7)*32+f]=x1.w;
    }
    __syncthreads();

    // ---- phase A: [32x64] @ [64x256] -> Q,K,V,Res  (FFMA2, 8x4 tiles) ----
    // Weights read straight from gmem (warp-uniform matrix; identical across
    // CTAs -> L1/L2 resident). Rows vary within quad (broadcast LDS),
    // cols shared by 4 lanes (8 distinct 16B lines -> 1 wf).
    {
        const int rt = lane & 3;                       // row tile 0..3
        const int f0 = rt * 8;
        const int c0 = warp * 32 + (lane >> 2) * 4;    // global col base
        // warp-uniform weight source: warps 0-1 Q, 2-3 K, 4-5 V, 6-7 R
        const int m = warp >> 1;
        const float* Wsrc = (m == 0) ? Wq : (m == 1) ? Wk : (m == 2) ? Wv : Wr;
        const float* wp_g = Wsrc + (c0 & 63);          // + k*64 per iter

        u64 acc[4][4];
        #pragma unroll
        for (int j = 0; j < 4; j++)
            #pragma unroll
            for (int cc = 0; cc < 4; cc++) acc[j][cc] = 0ULL;

        #pragma unroll 4
        for (int k = 0; k < 64; k++) {
            const ulonglong2* xt2 = (const ulonglong2*)(XT + k * 32);
            ulonglong2 xa = xt2[rt * 2];        // pairs (f0,f0+1),(f0+2,f0+3)
            ulonglong2 xb = xt2[rt * 2 + 1];    // pairs (f0+4..f0+7)
            float4 w4 = *(const float4*)(wp_g + k * 64);
            u64 wp0, wp1, wp2, wp3;
            PACK2(wp0, w4.x); PACK2(wp1, w4.y); PACK2(wp2, w4.z); PACK2(wp3, w4.w);
            FMA2(acc[0][0], xa.x, wp0); FMA2(acc[0][1], xa.x, wp1);
            FMA2(acc[0][2], xa.x, wp2); FMA2(acc[0][3], xa.x, wp3);
            FMA2(acc[1][0], xa.y, wp0); FMA2(acc[1][1], xa.y, wp1);
            FMA2(acc[1][2], xa.y, wp2); FMA2(acc[1][3], xa.y, wp3);
            FMA2(acc[2][0], xb.x, wp0); FMA2(acc[2][1], xb.x, wp1);
            FMA2(acc[2][2], xb.x, wp2); FMA2(acc[2][3], xb.x, wp3);
            FMA2(acc[3][0], xb.y, wp0); FMA2(acc[3][1], xb.y, wp1);
            FMA2(acc[3][2], xb.y, wp2); FMA2(acc[3][3], xb.y, wp3);
        }
        // Epilogue (branch warp-uniform: each warp covers 32 consecutive cols)
        #pragma unroll
        for (int j = 0; j < 4; j++) {
            #pragma unroll
            for (int cc = 0; cc < 4; cc++) {
                float lo, hi;
                UNPACK2(lo, hi, acc[j][cc]);
                const int c  = c0 + cc;
                const int fA = f0 + 2 * j;     // even -> 8B-aligned float2 slots
                if (c < 64) {                  // Q -> transposed qsT[h][a][f]
                    int h = c >> 5, a = c & 31;
                    *(float2*)(qsT + (h*32+a)*34 + fA) = make_float2(lo, hi);
                } else if (c < 128) {          // K -> transposed kT[h][a][g]
                    int e = c - 64, h = e >> 5, a = e & 31;
                    *(float2*)(kT + (h*32+a)*36 + fA) = make_float2(lo, hi);
                } else if (c < 192) {          // V natural vs[h][f][a]
                    int e = c - 128, h = e >> 5, a = e & 31;
                    vs[(h*32+fA)*32 + a]   = lo;
                    vs[(h*32+fA+1)*32 + a] = hi;
                } else {                       // Res natural
                    int e = c - 192;
                    res[fA*68 + e]     = lo;
                    res[(fA+1)*68 + e] = hi;
                }
            }
        }
    }
    __syncthreads();

    // ---- phase B+C fused: scores + softmax in registers/shuffles ----
    // Thread owns rows (fr0,fr0+1) x cols [c0b,c0b+4). A full score row lives
    // in one aligned 8-lane subgroup -> subwarp shfl reductions, write attn
    // transposed (atT[h][g][f]) directly.
    const int h   = tid >> 7;
    const int t   = tid & 127;
    const int fr0 = (t >> 3) * 2;       // even row pair base
    const int c0b = (t & 7) * 4;        // 4-wide col segment
    const unsigned gmask = 0xFFu << (lane & 24);
    {
        u64 accb[4] = {0ULL,0ULL,0ULL,0ULL};
        #pragma unroll 8
        for (int a = 0; a < 32; a++) {
            u64 q2 = *(const u64*)(qsT + (h*32+a)*34 + fr0);   // (f,f+1) pair
            float4 kv = *(const float4*)(kT + (h*32+a)*36 + c0b);
            u64 k0, k1, k2, k3;
            PACK2(k0, kv.x); PACK2(k1, kv.y); PACK2(k2, kv.z); PACK2(k3, kv.w);
            FMA2(accb[0], q2, k0); FMA2(accb[1], q2, k1);
            FMA2(accb[2], q2, k2); FMA2(accb[3], q2, k3);
        }
        float s0a,s0b,s1a,s1b,s2a,s2b,s3a,s3b;   // sNa=row fr0, sNb=row fr0+1
        UNPACK2(s0a, s0b, accb[0]); UNPACK2(s1a, s1b, accb[1]);
        UNPACK2(s2a, s2b, accb[2]); UNPACK2(s3a, s3b, accb[3]);

        float mA = fmaxf(fmaxf(s0a, s1a), fmaxf(s2a, s3a));
        float mB = fmaxf(fmaxf(s0b, s1b), fmaxf(s2b, s3b));
        #pragma unroll
        for (int o = 1; o < 8; o <<= 1) {
            mA = fmaxf(mA, __shfl_xor_sync(gmask, mA, o));
            mB = fmaxf(mB, __shfl_xor_sync(gmask, mB, o));
        }
        float e0a = __expf(s0a - mA), e1a = __expf(s1a - mA);
        float e2a = __expf(s2a - mA), e3a = __expf(s3a - mA);
        float e0b = __expf(s0b - mB), e1b = __expf(s1b - mB);
        float e2b = __expf(s2b - mB), e3b = __expf(s3b - mB);
        float sA = (e0a + e1a) + (e2a + e3a);
        float sB = (e0b + e1b) + (e2b + e3b);
        #pragma unroll
        for (int o = 1; o < 8; o <<= 1) {
            sA += __shfl_xor_sync(gmask, sA, o);
            sB += __shfl_xor_sync(gmask, sB, o);
        }
        float rA = __fdividef(1.f, sA), rB = __fdividef(1.f, sB);
        *(float2*)(atT + (h*32+c0b+0)*34 + fr0) = make_float2(e0a*rA, e0b*rB);
        *(float2*)(atT + (h*32+c0b+1)*34 + fr0) = make_float2(e1a*rA, e1b*rB);
        *(float2*)(atT + (h*32+c0b+2)*34 + fr0) = make_float2(e2a*rA, e2b*rB);
        *(float2*)(atT + (h*32+c0b+3)*34 + fr0) = make_float2(e3a*rA, e3b*rB);
    }
    __syncthreads();

    // ---- phase D: out = attn @ V + res, relu, store ----
    {
        u64 accd[4] = {0ULL,0ULL,0ULL,0ULL};
        #pragma unroll 8
        for (int g = 0; g < 32; g++) {
            u64 a2 = *(const u64*)(atT + (h*32+g)*34 + fr0);   // (f,f+1) pair
            float4 vv = *(const float4*)(vs + (h*32+g)*32 + c0b);
            u64 v0, v1, v2, v3;
            PACK2(v0, vv.x); PACK2(v1, vv.y); PACK2(v2, vv.z); PACK2(v3, vv.w);
            FMA2(accd[0], a2, v0); FMA2(accd[1], a2, v1);
            FMA2(accd[2], a2, v2); FMA2(accd[3], a2, v3);
        }
        float a0,b0,a1,b1,a2,b2,a3,b3;
        UNPACK2(a0, b0, accd[0]); UNPACK2(a1, b1, accd[1]);
        UNPACK2(a2, b2, accd[2]); UNPACK2(a3, b3, accd[3]);

        const int e0 = h * 32 + c0b;
        const float4 r0 = *(const float4*)(res + fr0*68 + e0);
        const float4 r1 = *(const float4*)(res + (fr0+1)*68 + e0);
        a0 = fmaxf(a0 + r0.x, 0.f); a1 = fmaxf(a1 + r0.y, 0.f);
        a2 = fmaxf(a2 + r0.z, 0.f); a3 = fmaxf(a3 + r0.w, 0.f);
        b0 = fmaxf(b0 + r1.x, 0.f); b1 = fmaxf(b1 + r1.y, 0.f);
        b2 = fmaxf(b2 + r1.z, 0.f); b3 = fmaxf(b3 + r1.w, 0.f);

        float* outp = Out + b * 2048 + fr0 * 64 + e0;
        *(float4*)(outp)      = make_float4(a0, a1, a2, a3);
        *(float4*)(outp + 64) = make_float4(b0, b1, b2, b3);
    }
}

extern "C" void kernel_launch(void* const* d_in, const int* in_sizes, int n_in,
                              void* d_out, int out_size)
{
    const float* X  = (const float*)d_in[0];
    const float* Wq = (const float*)d_in[1];
    const float* Wk = (const float*)d_in[2];
    const float* Wv = (const float*)d_in[3];
    const float* Wr = (const float*)d_in[4];
    float* Out = (float*)d_out;

    const int nb = in_sizes[0] / 2048;          // 16384 batches
    const size_t smem = 10880 * sizeof(float);  // 43520 B

    cudaFuncSetAttribute(interact_kernel,
                         cudaFuncAttributeMaxDynamicSharedMemorySize, (int)smem);
    interact_kernel<<<nb, 256, smem>>>(X, Wq, Wk, Wv, Wr, Out);
}

// round 9
// speedup vs baseline: 2.0207x; 1.5355x over previous
#include <cuda_runtime.h>

// Packed fp32x2 helpers (SASS FFMA2 path — PTX-only, sm_100+)
#define PACK2(d, s)        asm("mov.b64 %0, {%1, %1};" : "=l"(d) : "f"(s))
#define UNPACK2(lo, hi, s) asm("mov.b64 {%0, %1}, %2;" : "=f"(lo), "=f"(hi) : "l"(s))
#define FMA2(d, a, b)      asm("fma.rn.f32x2 %0, %1, %2, %0;" : "+l"(d) : "l"(a), "l"(b))

typedef unsigned long long u64;

__device__ __forceinline__ unsigned f2tf32(float x) {
    unsigned r; asm("cvt.rna.tf32.f32 %0, %1;" : "=r"(r) : "f"(x)); return r;
}

// D(16x8,f32) += A(16x8,tf32 row) * B(8x8,tf32 col)
__device__ __forceinline__ void mma_tf32(float* d, const uint4& a,
                                         unsigned b0, unsigned b1) {
    asm("mma.sync.aligned.m16n8k8.row.col.f32.tf32.tf32.f32 "
        "{%0,%1,%2,%3}, {%4,%5,%6,%7}, {%8,%9}, {%0,%1,%2,%3};"
        : "+f"(d[0]), "+f"(d[1]), "+f"(d[2]), "+f"(d[3])
        : "r"(a.x), "r"(a.y), "r"(a.z), "r"(a.w), "r"(b0), "r"(b1));
}

// Shared memory layout (floats), 11136 floats = 44544 B -> 3 CTAs/SM:
//   [0,2176)      xfrag[8 kc][2 mt][32 lane][4]  A fragments (tf32 bits), 2048 used
//                 aliased after phase A: atT[2][32][34] attn transposed
//   [2176,4352)   qsT[2][32][34]   Q transposed: qsT[h][a][f] (pad 34)
//   [4352,6656)   kT [2][32][36]   K transposed: kT[h][a][g] (pad 36)
//   [6656,8960)   vs [2][32][36]   V natural: vs[h][g][e] (pad 36)
//   [8960,11136)  res[32][68]      X@Wr (pad 68)

__global__ void __launch_bounds__(256, 3)
interact_kernel(const float* __restrict__ X,
                const float* __restrict__ Wq,
                const float* __restrict__ Wk,
                const float* __restrict__ Wv,
                const float* __restrict__ Wr,
                float* __restrict__ Out)
{
    extern __shared__ float sm[];
    float* xfrag = sm;         // phase A only
    float* atT   = sm;         // alias, written in fused B+C
    float* qsT   = sm + 2176;
    float* kT    = sm + 4352;
    float* vs    = sm + 6656;
    float* res   = sm + 8960;

    const int tid  = threadIdx.x;
    const int lane = tid & 31;
    const int warp = tid >> 5;
    const int lq   = lane >> 2;     // 0..7
    const int lr   = lane & 3;      // 0..3
    const long b   = blockIdx.x;

    // ---- stage X -> A-fragment layout (tf32-converted) ----
    // fragment fid = (kc*2+mt)*32 + lane_f holds {X[m][k],X[m+8][k],X[m][k+4],X[m+8][k+4]}
    // with m = mt*16 + lane_f>>2, k = kc*8 + lane_f&3.
    {
        const float* Xb = X + b * 2048;
        unsigned* xf = (unsigned*)xfrag;
        #pragma unroll
        for (int rep = 0; rep < 2; rep++) {
            int fid = tid + rep * 256;
            int kc = fid >> 6;
            int mt = (fid >> 5) & 1;
            int lf = fid & 31;
            int m  = mt * 16 + (lf >> 2);
            int k  = kc * 8 + (lf & 3);
            unsigned r0 = f2tf32(Xb[m * 64 + k]);
            unsigned r1 = f2tf32(Xb[(m + 8) * 64 + k]);
            unsigned r2 = f2tf32(Xb[m * 64 + k + 4]);
            unsigned r3 = f2tf32(Xb[(m + 8) * 64 + k + 4]);
            *(uint4*)(xf + fid * 4) = make_uint4(r0, r1, r2, r3);
        }
    }
    __syncthreads();

    // ---- phase A: [32x64]@[64x256] via tf32 mma.sync (tensor pipe) ----
    // Warp w covers 32 cols of one matrix: w>>1 selects Wq/Wk/Wv/Wr, w&1 the half.
    {
        const int msel  = warp >> 1;
        const float* Wsrc = (msel == 0) ? Wq : (msel == 1) ? Wk : (msel == 2) ? Wv : Wr;
        const int ncol0 = (warp & 1) * 32;

        float acc[2][4][4];
        #pragma unroll
        for (int mt = 0; mt < 2; mt++)
            #pragma unroll
            for (int nt = 0; nt < 4; nt++)
                #pragma unroll
                for (int r = 0; r < 4; r++) acc[mt][nt][r] = 0.f;

        const uint4* xf = (const uint4*)xfrag;
        #pragma unroll
        for (int kc = 0; kc < 8; kc++) {
            uint4 A0 = xf[(kc * 2 + 0) * 32 + lane];
            uint4 A1 = xf[(kc * 2 + 1) * 32 + lane];
            const int kb = kc * 8 + lr;
            #pragma unroll
            for (int nt = 0; nt < 4; nt++) {
                int n = ncol0 + nt * 8 + lq;
                unsigned b0 = f2tf32(Wsrc[kb * 64 + n]);
                unsigned b1 = f2tf32(Wsrc[(kb + 4) * 64 + n]);
                mma_tf32(acc[0][nt], A0, b0, b1);
                mma_tf32(acc[1][nt], A1, b0, b1);
            }
        }

        // epilogue: D frag (m0,cw),(m0,cw+1),(m0+8,cw),(m0+8,cw+1)
        #pragma unroll
        for (int mt = 0; mt < 2; mt++) {
            const int m0 = mt * 16 + lq;
            #pragma unroll
            for (int nt = 0; nt < 4; nt++) {
                const float c0 = acc[mt][nt][0], c1 = acc[mt][nt][1];
                const float c2 = acc[mt][nt][2], c3 = acc[mt][nt][3];
                const int cw = nt * 8 + lr * 2;          // col within 32-slice
                if (msel == 0) {                         // Q -> qsT[h][a][f]
                    int base = ((warp & 1) * 32 + cw) * 34;
                    qsT[base + m0]          = c0;
                    qsT[base + 34 + m0]     = c1;
                    qsT[base + m0 + 8]      = c2;
                    qsT[base + 34 + m0 + 8] = c3;
                } else if (msel == 1) {                  // K -> kT[h][a][g]
                    int base = ((warp & 1) * 32 + cw) * 36;
                    kT[base + m0]          = c0;
                    kT[base + 36 + m0]     = c1;
                    kT[base + m0 + 8]      = c2;
                    kT[base + 36 + m0 + 8] = c3;
                } else if (msel == 2) {                  // V -> vs[h][g][e] (pad36)
                    int h = warp & 1;
                    *(float2*)(vs + (h * 32 + m0) * 36 + cw)     = make_float2(c0, c1);
                    *(float2*)(vs + (h * 32 + m0 + 8) * 36 + cw) = make_float2(c2, c3);
                } else {                                 // Res -> res[f][e]
                    int e = (warp & 1) * 32 + cw;
                    *(float2*)(res + m0 * 68 + e)       = make_float2(c0, c1);
                    *(float2*)(res + (m0 + 8) * 68 + e) = make_float2(c2, c3);
                }
            }
        }
    }
    __syncthreads();

    // ---- phase B+C fused: scores + softmax in registers/shuffles ----
    const int h   = tid >> 7;
    const int t   = tid & 127;
    const int fr0 = (t >> 3) * 2;       // even row pair base
    const int c0b = (t & 7) * 4;        // 4-wide col segment
    const unsigned gmask = 0xFFu << (lane & 24);
    {
        u64 accb[4] = {0ULL,0ULL,0ULL,0ULL};
        #pragma unroll 8
        for (int a = 0; a < 32; a++) {
            u64 q2 = *(const u64*)(qsT + (h*32+a)*34 + fr0);   // (f,f+1) pair
            float4 kv = *(const float4*)(kT + (h*32+a)*36 + c0b);
            u64 k0, k1, k2, k3;
            PACK2(k0, kv.x); PACK2(k1, kv.y); PACK2(k2, kv.z); PACK2(k3, kv.w);
            FMA2(accb[0], q2, k0); FMA2(accb[1], q2, k1);
            FMA2(accb[2], q2, k2); FMA2(accb[3], q2, k3);
        }
        float s0a,s0b,s1a,s1b,s2a,s2b,s3a,s3b;
        UNPACK2(s0a, s0b, accb[0]); UNPACK2(s1a, s1b, accb[1]);
        UNPACK2(s2a, s2b, accb[2]); UNPACK2(s3a, s3b, accb[3]);

        float mA = fmaxf(fmaxf(s0a, s1a), fmaxf(s2a, s3a));
        float mB = fmaxf(fmaxf(s0b, s1b), fmaxf(s2b, s3b));
        #pragma unroll
        for (int o = 1; o < 8; o <<= 1) {
            mA = fmaxf(mA, __shfl_xor_sync(gmask, mA, o));
            mB = fmaxf(mB, __shfl_xor_sync(gmask, mB, o));
        }
        float e0a = __expf(s0a - mA), e1a = __expf(s1a - mA);
        float e2a = __expf(s2a - mA), e3a = __expf(s3a - mA);
        float e0b = __expf(s0b - mB), e1b = __expf(s1b - mB);
        float e2b = __expf(s2b - mB), e3b = __expf(s3b - mB);
        float sA = (e0a + e1a) + (e2a + e3a);
        float sB = (e0b + e1b) + (e2b + e3b);
        #pragma unroll
        for (int o = 1; o < 8; o <<= 1) {
            sA += __shfl_xor_sync(gmask, sA, o);
            sB += __shfl_xor_sync(gmask, sB, o);
        }
        float rA = __fdividef(1.f, sA), rB = __fdividef(1.f, sB);
        *(float2*)(atT + (h*32+c0b+0)*34 + fr0) = make_float2(e0a*rA, e0b*rB);
        *(float2*)(atT + (h*32+c0b+1)*34 + fr0) = make_float2(e1a*rA, e1b*rB);
        *(float2*)(atT + (h*32+c0b+2)*34 + fr0) = make_float2(e2a*rA, e2b*rB);
        *(float2*)(atT + (h*32+c0b+3)*34 + fr0) = make_float2(e3a*rA, e3b*rB);
    }
    __syncthreads();

    // ---- phase D: out = attn @ V + res, relu, store ----
    {
        u64 accd[4] = {0ULL,0ULL,0ULL,0ULL};
        #pragma unroll 8
        for (int g = 0; g < 32; g++) {
            u64 a2 = *(const u64*)(atT + (h*32+g)*34 + fr0);   // (f,f+1) pair
            float4 vv = *(const float4*)(vs + (h*32+g)*36 + c0b);
            u64 v0, v1, v2, v3;
            PACK2(v0, vv.x); PACK2(v1, vv.y); PACK2(v2, vv.z); PACK2(v3, vv.w);
            FMA2(accd[0], a2, v0); FMA2(accd[1], a2, v1);
            FMA2(accd[2], a2, v2); FMA2(accd[3], a2, v3);
        }
        float a0,b0,a1,b1,a2,b2,a3,b3;
        UNPACK2(a0, b0, accd[0]); UNPACK2(a1, b1, accd[1]);
        UNPACK2(a2, b2, accd[2]); UNPACK2(a3, b3, accd[3]);

        const int e0 = h * 32 + c0b;
        const float4 r0 = *(const float4*)(res + fr0*68 + e0);
        const float4 r1 = *(const float4*)(res + (fr0+1)*68 + e0);
        a0 = fmaxf(a0 + r0.x, 0.f); a1 = fmaxf(a1 + r0.y, 0.f);
        a2 = fmaxf(a2 + r0.z, 0.f); a3 = fmaxf(a3 + r0.w, 0.f);
        b0 = fmaxf(b0 + r1.x, 0.f); b1 = fmaxf(b1 + r1.y, 0.f);
        b2 = fmaxf(b2 + r1.z, 0.f); b3 = fmaxf(b3 + r1.w, 0.f);

        float* outp = Out + b * 2048 + fr0 * 64 + e0;
        *(float4*)(outp)      = make_float4(a0, a1, a2, a3);
        *(float4*)(outp + 64) = make_float4(b0, b1, b2, b3);
    }
}

extern "C" void kernel_launch(void* const* d_in, const int* in_sizes, int n_in,
                              void* d_out, int out_size)
{
    const float* X  = (const float*)d_in[0];
    const float* Wq = (const float*)d_in[1];
    const float* Wk = (const float*)d_in[2];
    const float* Wv = (const float*)d_in[3];
    const float* Wr = (const float*)d_in[4];
    float* Out = (float*)d_out;

    const int nb = in_sizes[0] / 2048;          // 16384 batches
    const size_t smem = 11136 * sizeof(float);  // 44544 B

    cudaFuncSetAttribute(interact_kernel,
                         cudaFuncAttributeMaxDynamicSharedMemorySize, (int)smem);
    interact_kernel<<<nb, 256, smem>>>(X, Wq, Wk, Wv, Wr, Out);
}

// round 11
// speedup vs baseline: 2.6013x; 1.2873x over previous
#include <cuda_runtime.h>

typedef unsigned long long u64;

__device__ __forceinline__ unsigned f2tf32(float x) {
    unsigned r; asm("cvt.rna.tf32.f32 %0, %1;" : "=r"(r) : "f"(x)); return r;
}

// 3xTF32 split: x ~= hi + lo, both tf32-representable
__device__ __forceinline__ void split_tf32(float x, unsigned& hi, unsigned& lo) {
    hi = f2tf32(x);
    lo = f2tf32(x - __uint_as_float(hi));
}

// D(16x8,f32) += A(16x8,tf32 row) * B(8x8,tf32 col)
__device__ __forceinline__ void mma_tf32(float* d, const uint4& a,
                                         unsigned b0, unsigned b1) {
    asm("mma.sync.aligned.m16n8k8.row.col.f32.tf32.tf32.f32 "
        "{%0,%1,%2,%3}, {%4,%5,%6,%7}, {%8,%9}, {%0,%1,%2,%3};"
        : "+f"(d[0]), "+f"(d[1]), "+f"(d[2]), "+f"(d[3])
        : "r"(a.x), "r"(a.y), "r"(a.z), "r"(a.w), "r"(b0), "r"(b1));
}

// Shared memory layout (floats), 11904 floats = 47616 B -> 3 CTAs/SM:
//   [0,2304)      xfrag[8 kc][2 mt][32 lane][4]  A fragments (2048 used, phase A)
//                 aliased after phase A: at[2][32][36]  attn: at[h][f][g] pad 36
//   [2304,4608)   qs [2][32][36]   Q: qs[h][f][a]  (pad 36)
//   [4608,7168)   kT [2][32][40]   K^T: kT[h][a][g] (pad 40)
//   [7168,9728)   vs [2][32][40]   V: vs[h][g][e]   (pad 40)
//   [9728,11904)  res[32][68]      X@Wr (pad 68)

__global__ void __launch_bounds__(256, 3)
interact_kernel(const float* __restrict__ X,
                const float* __restrict__ Wq,
                const float* __restrict__ Wk,
                const float* __restrict__ Wv,
                const float* __restrict__ Wr,
                float* __restrict__ Out)
{
    extern __shared__ float sm[];
    float* xfrag = sm;         // phase A only
    float* at    = sm;         // alias, written in fused B+C
    float* qs    = sm + 2304;
    float* kT    = sm + 4608;
    float* vs    = sm + 7168;
    float* res   = sm + 9728;

    const int tid  = threadIdx.x;
    const int lane = tid & 31;
    const int warp = tid >> 5;
    const int lq   = lane >> 2;     // 0..7
    const int lr   = lane & 3;      // 0..3
    const long b   = blockIdx.x;

    // ---- stage X -> A-fragment layout (tf32-converted) ----
    {
        const float* Xb = X + b * 2048;
        unsigned* xf = (unsigned*)xfrag;
        #pragma unroll
        for (int rep = 0; rep < 2; rep++) {
            int fid = tid + rep * 256;
            int kc = fid >> 6;
            int mt = (fid >> 5) & 1;
            int lf = fid & 31;
            int m  = mt * 16 + (lf >> 2);
            int k  = kc * 8 + (lf & 3);
            unsigned r0 = f2tf32(Xb[m * 64 + k]);
            unsigned r1 = f2tf32(Xb[(m + 8) * 64 + k]);
            unsigned r2 = f2tf32(Xb[m * 64 + k + 4]);
            unsigned r3 = f2tf32(Xb[(m + 8) * 64 + k + 4]);
            *(uint4*)(xf + fid * 4) = make_uint4(r0, r1, r2, r3);
        }
    }
    __syncthreads();

    // ---- phase A: [32x64]@[64x256] via tf32 mma (tensor pipe) ----
    {
        const int msel  = warp >> 1;
        const float* Wsrc = (msel == 0) ? Wq : (msel == 1) ? Wk : (msel == 2) ? Wv : Wr;
        const int hh    = warp & 1;         // 32-col half / head
        const int ncol0 = hh * 32;

        float acc[2][4][4];
        #pragma unroll
        for (int mt = 0; mt < 2; mt++)
            #pragma unroll
            for (int nt = 0; nt < 4; nt++)
                #pragma unroll
                for (int r = 0; r < 4; r++) acc[mt][nt][r] = 0.f;

        const uint4* xf = (const uint4*)xfrag;
        #pragma unroll
        for (int kc = 0; kc < 8; kc++) {
            uint4 A0 = xf[(kc * 2 + 0) * 32 + lane];
            uint4 A1 = xf[(kc * 2 + 1) * 32 + lane];
            const int kb = kc * 8 + lr;
            #pragma unroll
            for (int nt = 0; nt < 4; nt++) {
                int n = ncol0 + nt * 8 + lq;
                unsigned b0 = f2tf32(Wsrc[kb * 64 + n]);
                unsigned b1 = f2tf32(Wsrc[(kb + 4) * 64 + n]);
                mma_tf32(acc[0][nt], A0, b0, b1);
                mma_tf32(acc[1][nt], A1, b0, b1);
            }
        }

        // epilogue: D frag rows (m0, m0+8), cols (cw, cw+1)
        #pragma unroll
        for (int mt = 0; mt < 2; mt++) {
            const int m0 = mt * 16 + lq;
            #pragma unroll
            for (int nt = 0; nt < 4; nt++) {
                const float c0 = acc[mt][nt][0], c1 = acc[mt][nt][1];
                const float c2 = acc[mt][nt][2], c3 = acc[mt][nt][3];
                const int cw = nt * 8 + lr * 2;          // col within 32-slice
                if (msel == 0) {                         // Q -> qs[h][f][a]
                    *(float2*)(qs + ((hh<<5) + m0)*36 + cw)     = make_float2(c0, c1);
                    *(float2*)(qs + ((hh<<5) + m0 + 8)*36 + cw) = make_float2(c2, c3);
                } else if (msel == 1) {                  // K -> kT[h][a][g]
                    kT[((hh<<5) + cw    )*40 + m0]     = c0;
                    kT[((hh<<5) + cw + 1)*40 + m0]     = c1;
                    kT[((hh<<5) + cw    )*40 + m0 + 8] = c2;
                    kT[((hh<<5) + cw + 1)*40 + m0 + 8] = c3;
                } else if (msel == 2) {                  // V -> vs[h][g][e]
                    *(float2*)(vs + ((hh<<5) + m0)*40 + cw)     = make_float2(c0, c1);
                    *(float2*)(vs + ((hh<<5) + m0 + 8)*40 + cw) = make_float2(c2, c3);
                } else {                                 // Res -> res[f][e]
                    int e = (hh<<5) + cw;
                    *(float2*)(res + m0 * 68 + e)       = make_float2(c0, c1);
                    *(float2*)(res + (m0 + 8) * 68 + e) = make_float2(c2, c3);
                }
            }
        }
    }
    __syncthreads();

    // ---- phase B+C: scores via 3xTF32 mma + softmax in fragment domain ----
    // Warps 0-3: (h = warp>>1, mt = warp&1) -> M16(f) x N32(g) x K32(a)
    if (warp < 4) {
        const int h  = warp >> 1;
        const int f0 = (warp & 1) * 16;
        const float* qb = qs + (h << 5) * 36;
        const float* kb = kT + (h << 5) * 40;

        float acc[4][4];
        #pragma unroll
        for (int nt = 0; nt < 4; nt++)
            #pragma unroll
            for (int r = 0; r < 4; r++) acc[nt][r] = 0.f;

        #pragma unroll
        for (int kt = 0; kt < 4; kt++) {
            const int a0i = kt * 8 + lr;
            // A-frag from qs[f][a]: (f0+lq, a0i), (f0+lq+8, a0i), (.., a0i+4)
            float q0 = qb[(f0 + lq    )*36 + a0i];
            float q1 = qb[(f0 + lq + 8)*36 + a0i];
            float q2 = qb[(f0 + lq    )*36 + a0i + 4];
            float q3 = qb[(f0 + lq + 8)*36 + a0i + 4];
            uint4 Ah, Al;
            split_tf32(q0, Ah.x, Al.x); split_tf32(q1, Ah.y, Al.y);
            split_tf32(q2, Ah.z, Al.z); split_tf32(q3, Ah.w, Al.w);
            #pragma unroll
            for (int nt = 0; nt < 4; nt++) {
                const int g = nt * 8 + lq;
                float kv0 = kb[(a0i    )*40 + g];
                float kv1 = kb[(a0i + 4)*40 + g];
                unsigned bh0, bl0, bh1, bl1;
                split_tf32(kv0, bh0, bl0);
                split_tf32(kv1, bh1, bl1);
                mma_tf32(acc[nt], Ah, bh0, bh1);
                mma_tf32(acc[nt], Ah, bl0, bl1);
                mma_tf32(acc[nt], Al, bh0, bh1);
            }
        }

        // softmax: row rA = f0+lq (c0,c1), row rB = f0+lq+8 (c2,c3),
        // full row spans the 4 lanes of this quad -> shfl_xor 1,2
        const unsigned qm = 0xFu << (lane & 28);
        float mA = fmaxf(fmaxf(acc[0][0], acc[0][1]), fmaxf(acc[1][0], acc[1][1]));
        mA = fmaxf(mA, fmaxf(fmaxf(acc[2][0], acc[2][1]), fmaxf(acc[3][0], acc[3][1])));
        float mB = fmaxf(fmaxf(acc[0][2], acc[0][3]), fmaxf(acc[1][2], acc[1][3]));
        mB = fmaxf(mB, fmaxf(fmaxf(acc[2][2], acc[2][3]), fmaxf(acc[3][2], acc[3][3])));
        #pragma unroll
        for (int o = 1; o < 4; o <<= 1) {
            mA = fmaxf(mA, __shfl_xor_sync(qm, mA, o));
            mB = fmaxf(mB, __shfl_xor_sync(qm, mB, o));
        }
        float eA[4][2], eB[4][2], sA = 0.f, sB = 0.f;
        #pragma unroll
        for (int nt = 0; nt < 4; nt++) {
            eA[nt][0] = __expf(acc[nt][0] - mA); eA[nt][1] = __expf(acc[nt][1] - mA);
            eB[nt][0] = __expf(acc[nt][2] - mB); eB[nt][1] = __expf(acc[nt][3] - mB);
            sA += eA[nt][0] + eA[nt][1];
            sB += eB[nt][0] + eB[nt][1];
        }
        #pragma unroll
        for (int o = 1; o < 4; o <<= 1) {
            sA += __shfl_xor_sync(qm, sA, o);
            sB += __shfl_xor_sync(qm, sB, o);
        }
        float rA = __fdividef(1.f, sA), rB = __fdividef(1.f, sB);
        float* ab = at + (h << 5) * 36;
        #pragma unroll
        for (int nt = 0; nt < 4; nt++) {
            const int g = nt * 8 + 2 * lr;
            *(float2*)(ab + (f0 + lq    )*36 + g) = make_float2(eA[nt][0]*rA, eA[nt][1]*rA);
            *(float2*)(ab + (f0 + lq + 8)*36 + g) = make_float2(eB[nt][0]*rB, eB[nt][1]*rB);
        }
    }
    __syncthreads();

    // ---- phase D: out = attn @ V + res, relu (3xTF32 mma, 8 warps) ----
    {
        const int h   = warp >> 2;          // head
        const int f0  = ((warp >> 1) & 1) * 16;
        const int e0h = (warp & 1) * 16;    // e-half within head
        const float* ab = at + (h << 5) * 36;
        const float* vb = vs + (h << 5) * 40;

        float acc[2][4];
        #pragma unroll
        for (int nt = 0; nt < 2; nt++)
            #pragma unroll
            for (int r = 0; r < 4; r++) acc[nt][r] = 0.f;

        #pragma unroll
        for (int kt = 0; kt < 4; kt++) {
            const int g0 = kt * 8 + lr;
            float a0 = ab[(f0 + lq    )*36 + g0];
            float a1 = ab[(f0 + lq + 8)*36 + g0];
            float a2 = ab[(f0 + lq    )*36 + g0 + 4];
            float a3 = ab[(f0 + lq + 8)*36 + g0 + 4];
            uint4 Ah, Al;
            split_tf32(a0, Ah.x, Al.x); split_tf32(a1, Ah.y, Al.y);
            split_tf32(a2, Ah.z, Al.z); split_tf32(a3, Ah.w, Al.w);
            #pragma unroll
            for (int nt = 0; nt < 2; nt++) {
                const int e = e0h + nt * 8 + lq;
                float v0 = vb[(g0    )*40 + e];
                float v1 = vb[(g0 + 4)*40 + e];
                unsigned bh0, bl0, bh1, bl1;
                split_tf32(v0, bh0, bl0);
                split_tf32(v1, bh1, bl1);
                mma_tf32(acc[nt], Ah, bh0, bh1);
                mma_tf32(acc[nt], Ah, bl0, bl1);
                mma_tf32(acc[nt], Al, bh0, bh1);
            }
        }

        // epilogue: + res, relu, store
        #pragma unroll
        for (int nt = 0; nt < 2; nt++) {
            const int eg = (h << 5) + e0h + nt * 8 + 2 * lr;   // global e
            const int fA = f0 + lq, fB = f0 + lq + 8;
            float2 r0 = *(const float2*)(res + fA * 68 + eg);
            float2 r1 = *(const float2*)(res + fB * 68 + eg);
            float o0 = fmaxf(acc[nt][0] + r0.x, 0.f);
            float o1 = fmaxf(acc[nt][1] + r0.y, 0.f);
            float o2 = fmaxf(acc[nt][2] + r1.x, 0.f);
            float o3 = fmaxf(acc[nt][3] + r1.y, 0.f);
            *(float2*)(Out + b * 2048 + fA * 64 + eg) = make_float2(o0, o1);
            *(float2*)(Out + b * 2048 + fB * 64 + eg) = make_float2(o2, o3);
        }
    }
}

extern "C" void kernel_launch(void* const* d_in, const int* in_sizes, int n_in,
                              void* d_out, int out_size)
{
    const float* X  = (const float*)d_in[0];
    const float* Wq = (const float*)d_in[1];
    const float* Wk = (const float*)d_in[2];
    const float* Wv = (const float*)d_in[3];
    const float* Wr = (const float*)d_in[4];
    float* Out = (float*)d_out;

    const int nb = in_sizes[0] / 2048;          // 16384 batches
    const size_t smem = 11904 * sizeof(float);  // 47616 B

    cudaFuncSetAttribute(interact_kernel,
                         cudaFuncAttributeMaxDynamicSharedMemorySize, (int)smem);
    interact_kernel<<<nb, 256, smem>>>(X, Wq, Wk, Wv, Wr, Out);
}

// round 12
// speedup vs baseline: 2.8205x; 1.0843x over previous
#include <cuda_runtime.h>

typedef unsigned long long u64;

__device__ __forceinline__ unsigned f2tf32(float x) {
    unsigned r; asm("cvt.rna.tf32.f32 %0, %1;" : "=r"(r) : "f"(x)); return r;
}

// 3xTF32 split: x ~= hi + lo, both tf32-representable
__device__ __forceinline__ void split_tf32(float x, unsigned& hi, unsigned& lo) {
    hi = f2tf32(x);
    lo = f2tf32(x - __uint_as_float(hi));
}
__device__ __forceinline__ uint2 split2(float x) {
    uint2 r; r.x = f2tf32(x); r.y = f2tf32(x - __uint_as_float(r.x)); return r;
}

// D(16x8,f32) += A(16x8,tf32 row) * B(8x8,tf32 col)
__device__ __forceinline__ void mma_tf32(float* d, const uint4& a,
                                         unsigned b0, unsigned b1) {
    asm("mma.sync.aligned.m16n8k8.row.col.f32.tf32.tf32.f32 "
        "{%0,%1,%2,%3}, {%4,%5,%6,%7}, {%8,%9}, {%0,%1,%2,%3};"
        : "+f"(d[0]), "+f"(d[1]), "+f"(d[2]), "+f"(d[3])
        : "r"(a.x), "r"(a.y), "r"(a.z), "r"(a.w), "r"(b0), "r"(b1));
}

// Precomputed W fragment table: [w(8)][kc(8)][lane(32)][2] uint4
//   entry pair: uint4{b0 for nt=0..3}, uint4{b1 for nt=0..3}
//   w = msel*2 + hh : msel selects Wq/Wk/Wv/Wr, hh the 32-col half.
__device__ uint4 g_wtab[8 * 8 * 32 * 2];   // 64 KB

__global__ void wtab_init(const float* __restrict__ Wq,
                          const float* __restrict__ Wk,
                          const float* __restrict__ Wv,
                          const float* __restrict__ Wr)
{
    int gid = blockIdx.x * 256 + threadIdx.x;     // 0..2047
    int w    = gid >> 8;
    int kc   = (gid >> 5) & 7;
    int lane = gid & 31;
    int lq = lane >> 2, lr = lane & 3;
    int msel = w >> 1, hh = w & 1;
    const float* Ws = (msel == 0) ? Wq : (msel == 1) ? Wk : (msel == 2) ? Wv : Wr;
    uint4 b0v, b1v;
    unsigned* p0 = &b0v.x;
    unsigned* p1 = &b1v.x;
    #pragma unroll
    for (int nt = 0; nt < 4; nt++) {
        int n = hh * 32 + nt * 8 + lq;
        p0[nt] = f2tf32(Ws[(kc * 8 + lr    ) * 64 + n]);
        p1[nt] = f2tf32(Ws[(kc * 8 + lr + 4) * 64 + n]);
    }
    g_wtab[gid * 2]     = b0v;
    g_wtab[gid * 2 + 1] = b1v;
}

// Shared memory (floats), 16000 floats = 64000 B -> 3 CTAs/SM:
//   [0,2304)       xfrag[8 kc][2 mt][32 lane][4] (2048 used, phase A)
//                  aliased after A: at[2][32][36] attn f32
//   [2304,4608)    qs [2][32][36]    Q f32 (pad 36)
//   [4608,9216)    kT2[2][32 a][36]  K^T pre-split uint2(hi,lo), 32 g used
//   [9216,13824)   vs2[2][32 g][36]  V   pre-split uint2(hi,lo), 32 e used
//   [13824,16000)  res[32][68]       X@Wr f32 (pad 68)

__global__ void __launch_bounds__(256, 3)
interact_kernel(const float* __restrict__ X, float* __restrict__ Out)
{
    extern __shared__ float sm[];
    float* xfrag = sm;         // phase A only
    float* at    = sm;         // alias, written in fused B+C
    float* qs    = sm + 2304;
    uint2* kT2   = (uint2*)(sm + 4608);
    uint2* vs2   = (uint2*)(sm + 9216);
    float* res   = sm + 13824;

    const int tid  = threadIdx.x;
    const int lane = tid & 31;
    const int warp = tid >> 5;
    const int lq   = lane >> 2;     // 0..7
    const int lr   = lane & 3;      // 0..3
    const long b   = blockIdx.x;

    // ---- stage X -> A-fragment layout (tf32-converted) ----
    {
        const float* Xb = X + b * 2048;
        unsigned* xf = (unsigned*)xfrag;
        #pragma unroll
        for (int rep = 0; rep < 2; rep++) {
            int fid = tid + rep * 256;
            int kc = fid >> 6;
            int mt = (fid >> 5) & 1;
            int lf = fid & 31;
            int m  = mt * 16 + (lf >> 2);
            int k  = kc * 8 + (lf & 3);
            unsigned r0 = f2tf32(Xb[m * 64 + k]);
            unsigned r1 = f2tf32(Xb[(m + 8) * 64 + k]);
            unsigned r2 = f2tf32(Xb[m * 64 + k + 4]);
            unsigned r3 = f2tf32(Xb[(m + 8) * 64 + k + 4]);
            *(uint4*)(xf + fid * 4) = make_uint4(r0, r1, r2, r3);
        }
    }
    __syncthreads();

    // ---- phase A: [32x64]@[64x256] via tf32 mma, W frags pre-converted ----
    {
        const int msel = warp >> 1;
        const int hh   = warp & 1;

        float acc[2][4][4];
        #pragma unroll
        for (int mt = 0; mt < 2; mt++)
            #pragma unroll
            for (int nt = 0; nt < 4; nt++)
                #pragma unroll
                for (int r = 0; r < 4; r++) acc[mt][nt][r] = 0.f;

        const uint4* xf = (const uint4*)xfrag;
        const uint4* wt = g_wtab + (warp * 8 * 32 + lane) * 2;
        #pragma unroll
        for (int kc = 0; kc < 8; kc++) {
            uint4 A0 = xf[(kc * 2 + 0) * 32 + lane];
            uint4 A1 = xf[(kc * 2 + 1) * 32 + lane];
            uint4 B0 = wt[kc * 64];
            uint4 B1 = wt[kc * 64 + 1];
            const unsigned* b0p = &B0.x;
            const unsigned* b1p = &B1.x;
            #pragma unroll
            for (int nt = 0; nt < 4; nt++) {
                mma_tf32(acc[0][nt], A0, b0p[nt], b1p[nt]);
                mma_tf32(acc[1][nt], A1, b0p[nt], b1p[nt]);
            }
        }

        // epilogue: D frag rows (m0, m0+8), cols (cw, cw+1)
        #pragma unroll
        for (int mt = 0; mt < 2; mt++) {
            const int m0 = mt * 16 + lq;
            #pragma unroll
            for (int nt = 0; nt < 4; nt++) {
                const float c0 = acc[mt][nt][0], c1 = acc[mt][nt][1];
                const float c2 = acc[mt][nt][2], c3 = acc[mt][nt][3];
                const int cw = nt * 8 + lr * 2;
                if (msel == 0) {                         // Q -> qs[h][f][a] f32
                    *(float2*)(qs + ((hh<<5) + m0)*36 + cw)     = make_float2(c0, c1);
                    *(float2*)(qs + ((hh<<5) + m0 + 8)*36 + cw) = make_float2(c2, c3);
                } else if (msel == 1) {                  // K -> kT2[h][a=cw][g=m0] split
                    uint2* kb = kT2 + hh * 1152;
                    kb[(cw    )*36 + m0]     = split2(c0);
                    kb[(cw + 1)*36 + m0]     = split2(c1);
                    kb[(cw    )*36 + m0 + 8] = split2(c2);
                    kb[(cw + 1)*36 + m0 + 8] = split2(c3);
                } else if (msel == 2) {                  // V -> vs2[h][g=m0][e=cw] split
                    uint2* vb = vs2 + hh * 1152;
                    vb[(m0    )*36 + cw]     = split2(c0);
                    vb[(m0    )*36 + cw + 1] = split2(c1);
                    vb[(m0 + 8)*36 + cw]     = split2(c2);
                    vb[(m0 + 8)*36 + cw + 1] = split2(c3);
                } else {                                 // Res -> res[f][e] f32
                    int e = (hh<<5) + cw;
                    *(float2*)(res + m0 * 68 + e)       = make_float2(c0, c1);
                    *(float2*)(res + (m0 + 8) * 68 + e) = make_float2(c2, c3);
                }
            }
        }
    }
    __syncthreads();

    // ---- phase B+C: scores via 3xTF32 mma + softmax in fragment domain ----
    // Warps 0-3: (h = warp>>1, f-half = warp&1) -> M16(f) x N32(g) x K32(a)
    if (warp < 4) {
        const int h  = warp >> 1;
        const int f0 = (warp & 1) * 16;
        const float* qb = qs + (h << 5) * 36;
        const uint2* kb = kT2 + h * 1152;

        float acc[4][4];
        #pragma unroll
        for (int nt = 0; nt < 4; nt++)
            #pragma unroll
            for (int r = 0; r < 4; r++) acc[nt][r] = 0.f;

        #pragma unroll
        for (int kt = 0; kt < 4; kt++) {
            const int a0i = kt * 8 + lr;
            float q0 = qb[(f0 + lq    )*36 + a0i];
            float q1 = qb[(f0 + lq + 8)*36 + a0i];
            float q2 = qb[(f0 + lq    )*36 + a0i + 4];
            float q3 = qb[(f0 + lq + 8)*36 + a0i + 4];
            uint4 Ah, Al;
            split_tf32(q0, Ah.x, Al.x); split_tf32(q1, Ah.y, Al.y);
            split_tf32(q2, Ah.z, Al.z); split_tf32(q3, Ah.w, Al.w);
            #pragma unroll
            for (int nt = 0; nt < 4; nt++) {
                const int g = nt * 8 + lq;
                uint2 kv0 = kb[(a0i    )*36 + g];   // (hi,lo)
                uint2 kv1 = kb[(a0i + 4)*36 + g];
                mma_tf32(acc[nt], Ah, kv0.x, kv1.x);
                mma_tf32(acc[nt], Ah, kv0.y, kv1.y);
                mma_tf32(acc[nt], Al, kv0.x, kv1.x);
            }
        }

        // softmax in fragment domain: rows f0+lq / f0+lq+8 span the lane-quad
        const unsigned qm = 0xFu << (lane & 28);
        float mA = fmaxf(fmaxf(acc[0][0], acc[0][1]), fmaxf(acc[1][0], acc[1][1]));
        mA = fmaxf(mA, fmaxf(fmaxf(acc[2][0], acc[2][1]), fmaxf(acc[3][0], acc[3][1])));
        float mB = fmaxf(fmaxf(acc[0][2], acc[0][3]), fmaxf(acc[1][2], acc[1][3]));
        mB = fmaxf(mB, fmaxf(fmaxf(acc[2][2], acc[2][3]), fmaxf(acc[3][2], acc[3][3])));
        #pragma unroll
        for (int o = 1; o < 4; o <<= 1) {
            mA = fmaxf(mA, __shfl_xor_sync(qm, mA, o));
            mB = fmaxf(mB, __shfl_xor_sync(qm, mB, o));
        }
        float eA[4][2], eB[4][2], sA = 0.f, sB = 0.f;
        #pragma unroll
        for (int nt = 0; nt < 4; nt++) {
            eA[nt][0] = __expf(acc[nt][0] - mA); eA[nt][1] = __expf(acc[nt][1] - mA);
            eB[nt][0] = __expf(acc[nt][2] - mB); eB[nt][1] = __expf(acc[nt][3] - mB);
            sA += eA[nt][0] + eA[nt][1];
            sB += eB[nt][0] + eB[nt][1];
        }
        #pragma unroll
        for (int o = 1; o < 4; o <<= 1) {
            sA += __shfl_xor_sync(qm, sA, o);
            sB += __shfl_xor_sync(qm, sB, o);
        }
        float rA = __fdividef(1.f, sA), rB = __fdividef(1.f, sB);
        float* ab = at + (h << 5) * 36;
        #pragma unroll
        for (int nt = 0; nt < 4; nt++) {
            const int g = nt * 8 + 2 * lr;
            *(float2*)(ab + (f0 + lq    )*36 + g) = make_float2(eA[nt][0]*rA, eA[nt][1]*rA);
            *(float2*)(ab + (f0 + lq + 8)*36 + g) = make_float2(eB[nt][0]*rB, eB[nt][1]*rB);
        }
    }
    __syncthreads();

    // ---- phase D: out = attn @ V + res, relu (3xTF32 mma, 8 warps) ----
    {
        const int h   = warp >> 2;
        const int f0  = ((warp >> 1) & 1) * 16;
        const int e0h = (warp & 1) * 16;
        const float* ab = at + (h << 5) * 36;
        const uint2* vb = vs2 + h * 1152;

        float acc[2][4];
        #pragma unroll
        for (int nt = 0; nt < 2; nt++)
            #pragma unroll
            for (int r = 0; r < 4; r++) acc[nt][r] = 0.f;

        #pragma unroll
        for (int kt = 0; kt < 4; kt++) {
            const int g0 = kt * 8 + lr;
            float a0 = ab[(f0 + lq    )*36 + g0];
            float a1 = ab[(f0 + lq + 8)*36 + g0];
            float a2 = ab[(f0 + lq    )*36 + g0 + 4];
            float a3 = ab[(f0 + lq + 8)*36 + g0 + 4];
            uint4 Ah, Al;
            split_tf32(a0, Ah.x, Al.x); split_tf32(a1, Ah.y, Al.y);
            split_tf32(a2, Ah.z, Al.z); split_tf32(a3, Ah.w, Al.w);
            #pragma unroll
            for (int nt = 0; nt < 2; nt++) {
                const int e = e0h + nt * 8 + lq;
                uint2 v0 = vb[(g0    )*36 + e];
                uint2 v1 = vb[(g0 + 4)*36 + e];
                mma_tf32(acc[nt], Ah, v0.x, v1.x);
                mma_tf32(acc[nt], Ah, v0.y, v1.y);
                mma_tf32(acc[nt], Al, v0.x, v1.x);
            }
        }

        // epilogue: + res, relu, store
        #pragma unroll
        for (int nt = 0; nt < 2; nt++) {
            const int eg = (h << 5) + e0h + nt * 8 + 2 * lr;
            const int fA = f0 + lq, fB = f0 + lq + 8;
            float2 r0 = *(const float2*)(res + fA * 68 + eg);
            float2 r1 = *(const float2*)(res + fB * 68 + eg);
            float o0 = fmaxf(acc[nt][0] + r0.x, 0.f);
            float o1 = fmaxf(acc[nt][1] + r0.y, 0.f);
            float o2 = fmaxf(acc[nt][2] + r1.x, 0.f);
            float o3 = fmaxf(acc[nt][3] + r1.y, 0.f);
            *(float2*)(Out + b * 2048 + fA * 64 + eg) = make_float2(o0, o1);
            *(float2*)(Out + b * 2048 + fB * 64 + eg) = make_float2(o2, o3);
        }
    }
}

extern "C" void kernel_launch(void* const* d_in, const int* in_sizes, int n_in,
                              void* d_out, int out_size)
{
    const float* X  = (const float*)d_in[0];
    const float* Wq = (const float*)d_in[1];
    const float* Wk = (const float*)d_in[2];
    const float* Wv = (const float*)d_in[3];
    const float* Wr = (const float*)d_in[4];
    float* Out = (float*)d_out;

    const int nb = in_sizes[0] / 2048;          // 16384 batches
    const size_t smem = 16000 * sizeof(float);  // 64000 B

    wtab_init<<<8, 256>>>(Wq, Wk, Wv, Wr);

    cudaFuncSetAttribute(interact_kernel,
                         cudaFuncAttributeMaxDynamicSharedMemorySize, (int)smem);
    interact_kernel<<<nb, 256, smem>>>(X, Out);
}

// round 15
// speedup vs baseline: 2.9939x; 1.0615x over previous
#include <cuda_runtime.h>
#include <cuda_bf16.h>

typedef unsigned long long u64;

__device__ __forceinline__ unsigned f2tf32(float x) {
    unsigned r; asm("cvt.rna.tf32.f32 %0, %1;" : "=r"(r) : "f"(x)); return r;
}

// pack two floats to bf16x2 word (lo 16 bits = a, hi = b)
__device__ __forceinline__ unsigned bf2(float a, float b) {
    __nv_bfloat162 h = __floats2bfloat162_rn(a, b);
    return *(unsigned*)&h;
}
// pack + return residuals (for hi/lo split)
__device__ __forceinline__ unsigned bf2_hi(float a, float b, float& ra, float& rb) {
    __nv_bfloat162 h = __floats2bfloat162_rn(a, b);
    ra = a - __bfloat162float(h.x);
    rb = b - __bfloat162float(h.y);
    return *(unsigned*)&h;
}

// D(16x8,f32) += A(16x8,tf32 row) * B(8x8,tf32 col)
__device__ __forceinline__ void mma_tf32(float* d, const uint4& a,
                                         unsigned b0, unsigned b1) {
    asm("mma.sync.aligned.m16n8k8.row.col.f32.tf32.tf32.f32 "
        "{%0,%1,%2,%3}, {%4,%5,%6,%7}, {%8,%9}, {%0,%1,%2,%3};"
        : "+f"(d[0]), "+f"(d[1]), "+f"(d[2]), "+f"(d[3])
        : "r"(a.x), "r"(a.y), "r"(a.z), "r"(a.w), "r"(b0), "r"(b1));
}
// D(16x8,f32) += A(16x16,bf16 row) * B(16x8,bf16 col)
__device__ __forceinline__ void mma_bf16(float* d, const uint4& a,
                                         unsigned b0, unsigned b1) {
    asm("mma.sync.aligned.m16n8k16.row.col.f32.bf16.bf16.f32 "
        "{%0,%1,%2,%3}, {%4,%5,%6,%7}, {%8,%9}, {%0,%1,%2,%3};"
        : "+f"(d[0]), "+f"(d[1]), "+f"(d[2]), "+f"(d[3])
        : "r"(a.x), "r"(a.y), "r"(a.z), "r"(a.w), "r"(b0), "r"(b1));
}

// Precomputed W fragment table: [w(8)][kc(8)][lane(32)][2] uint4 (tf32)
__device__ uint4 g_wtab[8 * 8 * 32 * 2];   // 64 KB

__global__ void wtab_init(const float* __restrict__ Wq,
                          const float* __restrict__ Wk,
                          const float* __restrict__ Wv,
                          const float* __restrict__ Wr)
{
    int gid = blockIdx.x * 256 + threadIdx.x;     // 0..2047
    int w    = gid >> 8;
    int kc   = (gid >> 5) & 7;
    int lane = gid & 31;
    int lq = lane >> 2, lr = lane & 3;
    int msel = w >> 1, hh = w & 1;
    const float* Ws = (msel == 0) ? Wq : (msel == 1) ? Wk : (msel == 2) ? Wv : Wr;
    uint4 b0v, b1v;
    unsigned* p0 = &b0v.x;
    unsigned* p1 = &b1v.x;
    #pragma unroll
    for (int nt = 0; nt < 4; nt++) {
        int n = hh * 32 + nt * 8 + lq;
        p0[nt] = f2tf32(Ws[(kc * 8 + lr    ) * 64 + n]);
        p1[nt] = f2tf32(Ws[(kc * 8 + lr + 4) * 64 + n]);
    }
    g_wtab[gid * 2]     = b0v;
    g_wtab[gid * 2 + 1] = b1v;
}

// Shared memory: 11392 x 4B words = 45568 B -> 3 CTAs/SM.
// Word (4B) offsets:
//   [0,2304)      xfrag (phase A staging, 2048 used)
//                 aliased after A: ath[0,1152) + atl[1152,2304)
//                   attn hi/lo: bf16x2 words, [2 h][32 f][18 w] (g-pairs)
//   [2304,3456)   qh   Q hi  [2][32 f][18 w] (a-pairs)
//   [3456,4608)   ql   Q lo
//   [4608,5760)   kh   K hi  [2][32 g][18 w] (a-pairs)
//   [5760,6912)   kl   K lo
//   [6912,8064)   vth  V^T hi [2][32 e][18 w] (g-pairs)
//   [8064,9216)   vtl  V^T lo
//   [9216,11392)  res  f32 [32][68]
#define SW_ATH 0
#define SW_ATL 1152
#define SW_QH  2304
#define SW_QL  3456
#define SW_KH  4608
#define SW_KL  5760
#define SW_VTH 6912
#define SW_VTL 8064
#define SW_RES 9216

__global__ void __launch_bounds__(256, 3)
interact_kernel(const float* __restrict__ X, float* __restrict__ Out)
{
    extern __shared__ float sm[];
    unsigned* usm  = (unsigned*)sm;
    float* xfrag = sm;             // phase A only
    float* res   = sm + SW_RES;

    const int tid  = threadIdx.x;
    const int lane = tid & 31;
    const int warp = tid >> 5;
    const int lq   = lane >> 2;     // 0..7
    const int lr   = lane & 3;      // 0..3
    const long b   = blockIdx.x;

    // ---- stage X -> A-fragment layout (tf32-converted) ----
    {
        const float* Xb = X + b * 2048;
        unsigned* xf = (unsigned*)xfrag;
        #pragma unroll
        for (int rep = 0; rep < 2; rep++) {
            int fid = tid + rep * 256;
            int kc = fid >> 6;
            int mt = (fid >> 5) & 1;
            int lf = fid & 31;
            int m  = mt * 16 + (lf >> 2);
            int k  = kc * 8 + (lf & 3);
            unsigned r0 = f2tf32(Xb[m * 64 + k]);
            unsigned r1 = f2tf32(Xb[(m + 8) * 64 + k]);
            unsigned r2 = f2tf32(Xb[m * 64 + k + 4]);
            unsigned r3 = f2tf32(Xb[(m + 8) * 64 + k + 4]);
            *(uint4*)(xf + fid * 4) = make_uint4(r0, r1, r2, r3);
        }
    }
    __syncthreads();

    // ---- phase A: [32x64]@[64x256] via tf32 mma, W frags pre-converted ----
    {
        const int msel = warp >> 1;
        const int hh   = warp & 1;

        float acc[2][4][4];
        #pragma unroll
        for (int mt = 0; mt < 2; mt++)
            #pragma unroll
            for (int nt = 0; nt < 4; nt++)
                #pragma unroll
                for (int r = 0; r < 4; r++) acc[mt][nt][r] = 0.f;

        const uint4* xf = (const uint4*)xfrag;
        const uint4* wt = g_wtab + (warp * 8 * 32 + lane) * 2;
        #pragma unroll
        for (int kc = 0; kc < 8; kc++) {
            uint4 A0 = xf[(kc * 2 + 0) * 32 + lane];
            uint4 A1 = xf[(kc * 2 + 1) * 32 + lane];
            uint4 B0 = wt[kc * 64];
            uint4 B1 = wt[kc * 64 + 1];
            const unsigned* b0p = &B0.x;
            const unsigned* b1p = &B1.x;
            #pragma unroll
            for (int nt = 0; nt < 4; nt++) {
                mma_tf32(acc[0][nt], A0, b0p[nt], b1p[nt]);
                mma_tf32(acc[1][nt], A1, b0p[nt], b1p[nt]);
            }
        }

        // epilogue: split into bf16 hi/lo shared arrays
        #pragma unroll
        for (int mt = 0; mt < 2; mt++) {
            const int m0 = mt * 16 + lq;
            #pragma unroll
            for (int nt = 0; nt < 4; nt++) {
                const float c0 = acc[mt][nt][0], c1 = acc[mt][nt][1];
                const float c2 = acc[mt][nt][2], c3 = acc[mt][nt][3];
                const int cw = nt * 8 + lr * 2;
                if (msel == 0) {                   // Q: qh/ql rows f, a-pairs
                    const int r0 = (hh*32 + m0)*18 + (cw >> 1);
                    const int r1 = (hh*32 + m0 + 8)*18 + (cw >> 1);
                    float l0, l1, l2, l3;
                    unsigned h01 = bf2_hi(c0, c1, l0, l1);
                    unsigned h23 = bf2_hi(c2, c3, l2, l3);
                    usm[SW_QH + r0] = h01;  usm[SW_QL + r0] = bf2(l0, l1);
                    usm[SW_QH + r1] = h23;  usm[SW_QL + r1] = bf2(l2, l3);
                } else if (msel == 1) {            // K: kh/kl rows g, a-pairs
                    const int r0 = (hh*32 + m0)*18 + (cw >> 1);
                    const int r1 = (hh*32 + m0 + 8)*18 + (cw >> 1);
                    float l0, l1, l2, l3;
                    unsigned h01 = bf2_hi(c0, c1, l0, l1);
                    unsigned h23 = bf2_hi(c2, c3, l2, l3);
                    usm[SW_KH + r0] = h01;  usm[SW_KL + r0] = bf2(l0, l1);
                    usm[SW_KH + r1] = h23;  usm[SW_KL + r1] = bf2(l2, l3);
                } else if (msel == 2) {            // V -> transposed vth/vtl[e][g]
                    __nv_bfloat16* vh = (__nv_bfloat16*)(usm + SW_VTH);
                    __nv_bfloat16* vl = (__nv_bfloat16*)(usm + SW_VTL);
                    const int base0 = (hh*32 + cw)     * 36;   // row e = cw
                    const int base1 = (hh*32 + cw + 1) * 36;   // row e = cw+1
                    __nv_bfloat16 h0 = __float2bfloat16_rn(c0);
                    __nv_bfloat16 h1 = __float2bfloat16_rn(c1);
                    __nv_bfloat16 h2 = __float2bfloat16_rn(c2);
                    __nv_bfloat16 h3 = __float2bfloat16_rn(c3);
                    vh[base0 + m0]     = h0;  vl[base0 + m0]     = __float2bfloat16_rn(c0 - __bfloat162float(h0));
                    vh[base1 + m0]     = h1;  vl[base1 + m0]     = __float2bfloat16_rn(c1 - __bfloat162float(h1));
                    vh[base0 + m0 + 8] = h2;  vl[base0 + m0 + 8] = __float2bfloat16_rn(c2 - __bfloat162float(h2));
                    vh[base1 + m0 + 8] = h3;  vl[base1 + m0 + 8] = __float2bfloat16_rn(c3 - __bfloat162float(h3));
                } else {                           // Res -> res[f][e] f32
                    int e = (hh<<5) + cw;
                    *(float2*)(res + m0 * 68 + e)       = make_float2(c0, c1);
                    *(float2*)(res + (m0 + 8) * 68 + e) = make_float2(c2, c3);
                }
            }
        }
    }
    __syncthreads();

    // ---- phase B+C: scores via 3-term bf16 m16n8k16 + softmax ----
    // Warps 0-3: h = warp>>1, f-half = warp&1 -> M16(f) x N32(g) x K32(a)
    if (warp < 4) {
        const int h  = warp >> 1;
        const int f0 = (warp & 1) * 16;
        const unsigned* qhw = usm + SW_QH + h * 576;
        const unsigned* qlw = usm + SW_QL + h * 576;
        const unsigned* khw = usm + SW_KH + h * 576;
        const unsigned* klw = usm + SW_KL + h * 576;

        float acc[4][4];
        #pragma unroll
        for (int nt = 0; nt < 4; nt++)
            #pragma unroll
            for (int r = 0; r < 4; r++) acc[nt][r] = 0.f;

        #pragma unroll
        for (int kt = 0; kt < 2; kt++) {
            const int wo = kt * 8 + lr;
            uint4 Ah, Al;
            Ah.x = qhw[(f0 + lq    )*18 + wo];
            Ah.y = qhw[(f0 + lq + 8)*18 + wo];
            Ah.z = qhw[(f0 + lq    )*18 + wo + 4];
            Ah.w = qhw[(f0 + lq + 8)*18 + wo + 4];
            Al.x = qlw[(f0 + lq    )*18 + wo];
            Al.y = qlw[(f0 + lq + 8)*18 + wo];
            Al.z = qlw[(f0 + lq    )*18 + wo + 4];
            Al.w = qlw[(f0 + lq + 8)*18 + wo + 4];
            #pragma unroll
            for (int nt = 0; nt < 4; nt++) {
                const int gr = nt * 8 + lq;
                unsigned bh0 = khw[gr*18 + wo], bh1 = khw[gr*18 + wo + 4];
                unsigned bl0 = klw[gr*18 + wo], bl1 = klw[gr*18 + wo + 4];
                mma_bf16(acc[nt], Ah, bh0, bh1);
                mma_bf16(acc[nt], Ah, bl0, bl1);
                mma_bf16(acc[nt], Al, bh0, bh1);
            }
        }

        // softmax in fragment domain: rows f0+lq / f0+lq+8 span the lane-quad
        const unsigned qm = 0xFu << (lane & 28);
        float mA = fmaxf(fmaxf(acc[0][0], acc[0][1]), fmaxf(acc[1][0], acc[1][1]));
        mA = fmaxf(mA, fmaxf(fmaxf(acc[2][0], acc[2][1]), fmaxf(acc[3][0], acc[3][1])));
        float mB = fmaxf(fmaxf(acc[0][2], acc[0][3]), fmaxf(acc[1][2], acc[1][3]));
        mB = fmaxf(mB, fmaxf(fmaxf(acc[2][2], acc[2][3]), fmaxf(acc[3][2], acc[3][3])));
        #pragma unroll
        for (int o = 1; o < 4; o <<= 1) {
            mA = fmaxf(mA, __shfl_xor_sync(qm, mA, o));
            mB = fmaxf(mB, __shfl_xor_sync(qm, mB, o));
        }
        float eA[4][2], eB[4][2], sA = 0.f, sB = 0.f;
        #pragma unroll
        for (int nt = 0; nt < 4; nt++) {
            eA[nt][0] = __expf(acc[nt][0] - mA); eA[nt][1] = __expf(acc[nt][1] - mA);
            eB[nt][0] = __expf(acc[nt][2] - mB); eB[nt][1] = __expf(acc[nt][3] - mB);
            sA += eA[nt][0] + eA[nt][1];
            sB += eB[nt][0] + eB[nt][1];
        }
        #pragma unroll
        for (int o = 1; o < 4; o <<= 1) {
            sA += __shfl_xor_sync(qm, sA, o);
            sB += __shfl_xor_sync(qm, sB, o);
        }
        float rA = __fdividef(1.f, sA), rB = __fdividef(1.f, sB);

        // store attn as bf16 hi/lo, g-pairs: word (f)*18 + nt*4 + lr
        unsigned* athw = usm + SW_ATH + h * 576;
        unsigned* atlw = usm + SW_ATL + h * 576;
        #pragma unroll
        for (int nt = 0; nt < 4; nt++) {
            float v0 = eA[nt][0]*rA, v1 = eA[nt][1]*rA;   // row f0+lq
            float w0 = eB[nt][0]*rB, w1 = eB[nt][1]*rB;   // row f0+lq+8
            float l0, l1, l2, l3;
            unsigned hA = bf2_hi(v0, v1, l0, l1);
            unsigned hB = bf2_hi(w0, w1, l2, l3);
            athw[(f0 + lq    )*18 + nt*4 + lr] = hA;
            atlw[(f0 + lq    )*18 + nt*4 + lr] = bf2(l0, l1);
            athw[(f0 + lq + 8)*18 + nt*4 + lr] = hB;
            atlw[(f0 + lq + 8)*18 + nt*4 + lr] = bf2(l2, l3);
        }
    }
    __syncthreads();

    // ---- phase D: out = attn @ V + res, relu (3-term bf16, 8 warps) ----
    {
        const int h   = warp >> 2;
        const int f0  = ((warp >> 1) & 1) * 16;
        const int e0h = (warp & 1) * 16;
        const unsigned* athw = usm + SW_ATH + h * 576;
        const unsigned* atlw = usm + SW_ATL + h * 576;
        const unsigned* vthw = usm + SW_VTH + h * 576;
        const unsigned* vtlw = usm + SW_VTL + h * 576;

        float acc[2][4];
        #pragma unroll
        for (int nt = 0; nt < 2; nt++)
            #pragma unroll
            for (int r = 0; r < 4; r++) acc[nt][r] = 0.f;

        #pragma unroll
        for (int kt = 0; kt < 2; kt++) {
            const int wo = kt * 8 + lr;
            uint4 Ah, Al;
            Ah.x = athw[(f0 + lq    )*18 + wo];
            Ah.y = athw[(f0 + lq + 8)*18 + wo];
            Ah.z = athw[(f0 + lq    )*18 + wo + 4];
            Ah.w = athw[(f0 + lq + 8)*18 + wo + 4];
            Al.x = atlw[(f0 + lq    )*18 + wo];
            Al.y = atlw[(f0 + lq + 8)*18 + wo];
            Al.z = atlw[(f0 + lq    )*18 + wo + 4];
            Al.w = atlw[(f0 + lq + 8)*18 + wo + 4];
            #pragma unroll
            for (int nt = 0; nt < 2; nt++) {
                const int er = e0h + nt * 8 + lq;
                unsigned bh0 = vthw[er*18 + wo], bh1 = vthw[er*18 + wo + 4];
                unsigned bl0 = vtlw[er*18 + wo], bl1 = vtlw[er*18 + wo + 4];
                mma_bf16(acc[nt], Ah, bh0, bh1);
                mma_bf16(acc[nt], Ah, bl0, bl1);
                mma_bf16(acc[nt], Al, bh0, bh1);
            }
        }

        // epilogue: + res, relu, store
        #pragma unroll
        for (int nt = 0; nt < 2; nt++) {
            const int eg = (h << 5) + e0h + nt * 8 + 2 * lr;
            const int fA = f0 + lq, fB = f0 + lq + 8;
            float2 r0 = *(const float2*)(res + fA * 68 + eg);
            float2 r1 = *(const float2*)(res + fB * 68 + eg);
            float o0 = fmaxf(acc[nt][0] + r0.x, 0.f);
            float o1 = fmaxf(acc[nt][1] + r0.y, 0.f);
            float o2 = fmaxf(acc[nt][2] + r1.x, 0.f);
            float o3 = fmaxf(acc[nt][3] + r1.y, 0.f);
            *(float2*)(Out + b * 2048 + fA * 64 + eg) = make_float2(o0, o1);
            *(float2*)(Out + b * 2048 + fB * 64 + eg) = make_float2(o2, o3);
        }
    }
}

extern "C" void kernel_launch(void* const* d_in, const int* in_sizes, int n_in,
                              void* d_out, int out_size)
{
    const float* X  = (const float*)d_in[0];
    const float* Wq = (const float*)d_in[1];
    const float* Wk = (const float*)d_in[2];
    const float* Wv = (const float*)d_in[3];
    const float* Wr = (const float*)d_in[4];
    float* Out = (float*)d_out;

    const int nb = in_sizes[0] / 2048;          // 16384 batches
    const size_t smem = 11392 * sizeof(float);  // 45568 B

    wtab_init<<<8, 256>>>(Wq, Wk, Wv, Wr);

    cudaFuncSetAttribute(interact_kernel,
                         cudaFuncAttributeMaxDynamicSharedMemorySize, (int)smem);
    interact_kernel<<<nb, 256, smem>>>(X, Out);
}

// round 17
// speedup vs baseline: 3.5323x; 1.1798x over previous
#include <cuda_runtime.h>
#include <cuda_bf16.h>

typedef unsigned long long u64;

__device__ __forceinline__ unsigned f2tf32(float x) {
    unsigned r; asm("cvt.rna.tf32.f32 %0, %1;" : "=r"(r) : "f"(x)); return r;
}

// pack two floats to bf16x2 word (lo 16 bits = a, hi = b)
__device__ __forceinline__ unsigned bf2(float a, float b) {
    __nv_bfloat162 h = __floats2bfloat162_rn(a, b);
    return *(unsigned*)&h;
}
// pack + return residuals (for hi/lo split)
__device__ __forceinline__ unsigned bf2_hi(float a, float b, float& ra, float& rb) {
    __nv_bfloat162 h = __floats2bfloat162_rn(a, b);
    ra = a - __bfloat162float(h.x);
    rb = b - __bfloat162float(h.y);
    return *(unsigned*)&h;
}

// D(16x8,f32) += A(16x8,tf32 row) * B(8x8,tf32 col)
__device__ __forceinline__ void mma_tf32(float* d, const uint4& a,
                                         unsigned b0, unsigned b1) {
    asm("mma.sync.aligned.m16n8k8.row.col.f32.tf32.tf32.f32 "
        "{%0,%1,%2,%3}, {%4,%5,%6,%7}, {%8,%9}, {%0,%1,%2,%3};"
        : "+f"(d[0]), "+f"(d[1]), "+f"(d[2]), "+f"(d[3])
        : "r"(a.x), "r"(a.y), "r"(a.z), "r"(a.w), "r"(b0), "r"(b1));
}
// D(16x8,f32) += A(16x16,bf16 row) * B(16x8,bf16 col)
__device__ __forceinline__ void mma_bf16(float* d, const uint4& a,
                                         unsigned b0, unsigned b1) {
    asm("mma.sync.aligned.m16n8k16.row.col.f32.bf16.bf16.f32 "
        "{%0,%1,%2,%3}, {%4,%5,%6,%7}, {%8,%9}, {%0,%1,%2,%3};"
        : "+f"(d[0]), "+f"(d[1]), "+f"(d[2]), "+f"(d[3])
        : "r"(a.x), "r"(a.y), "r"(a.z), "r"(a.w), "r"(b0), "r"(b1));
}

// Precomputed W fragment table, warp-contiguous: [w(8)][kc(8)][2][lane(32)] uint4
// A warp's B0 (or B1) load is 512B contiguous -> 4 L1 wavefronts.
__device__ uint4 g_wtab[8 * 8 * 2 * 32];   // 64 KB

__global__ void wtab_init(const float* __restrict__ Wq,
                          const float* __restrict__ Wk,
                          const float* __restrict__ Wv,
                          const float* __restrict__ Wr)
{
    int gid = blockIdx.x * 256 + threadIdx.x;     // 0..2047
    int w    = gid >> 8;
    int kc   = (gid >> 5) & 7;
    int lane = gid & 31;
    int lq = lane >> 2, lr = lane & 3;
    int msel = w >> 1, hh = w & 1;
    const float* Ws = (msel == 0) ? Wq : (msel == 1) ? Wk : (msel == 2) ? Wv : Wr;
    uint4 b0v, b1v;
    unsigned* p0 = &b0v.x;
    unsigned* p1 = &b1v.x;
    #pragma unroll
    for (int nt = 0; nt < 4; nt++) {
        int n = hh * 32 + nt * 8 + lq;
        p0[nt] = f2tf32(Ws[(kc * 8 + lr    ) * 64 + n]);
        p1[nt] = f2tf32(Ws[(kc * 8 + lr + 4) * 64 + n]);
    }
    g_wtab[((w * 8 + kc) * 2 + 0) * 32 + lane] = b0v;
    g_wtab[((w * 8 + kc) * 2 + 1) * 32 + lane] = b1v;
}

// Shared memory: 12416 x 4B words = 49664 B -> 3 CTAs/SM.
// uint2 arrays hold interleaved (hi bf16x2, lo bf16x2); row stride 20 uint2
// (160 B) so fragment LDS.64s are conflict-free per half-warp phase.
// Word (4B) offsets:
//   [0,2560)       at2  attn [2 h][32 f][20 uint2] (g-pair words 0..15)
//                  (first 2048 words alias xfrag during phase A)
//   [2560,5120)    q2   Q    [2 h][32 f][20] (a-pairs)
//   [5120,7680)    k2   K    [2 h][32 g][20] (a-pairs)
//   [7680,10240)   vt2  V^T  [2 h][32 e][20] (g-pairs)
//   [10240,12416)  res  f32 [32][68]
#define SW_AT  0
#define SW_Q   2560
#define SW_K   5120
#define SW_VT  7680
#define SW_RES 10240

__global__ void __launch_bounds__(256, 3)
interact_kernel(const float* __restrict__ X, float* __restrict__ Out)
{
    extern __shared__ float sm[];
    unsigned* usm  = (unsigned*)sm;
    float* xfrag = sm;             // phase A only (aliases at2)
    float* res   = sm + SW_RES;
    uint2* at2   = (uint2*)(usm + SW_AT);
    uint2* q2a   = (uint2*)(usm + SW_Q);
    uint2* k2a   = (uint2*)(usm + SW_K);
    uint2* vt2   = (uint2*)(usm + SW_VT);

    const int tid  = threadIdx.x;
    const int lane = tid & 31;
    const int warp = tid >> 5;
    const int lq   = lane >> 2;     // 0..7
    const int lr   = lane & 3;      // 0..3
    const long b   = blockIdx.x;

    // ---- stage X -> A-fragment layout (tf32-converted) ----
    {
        const float* Xb = X + b * 2048;
        unsigned* xf = (unsigned*)xfrag;
        #pragma unroll
        for (int rep = 0; rep < 2; rep++) {
            int fid = tid + rep * 256;
            int kc = fid >> 6;
            int mt = (fid >> 5) & 1;
            int lf = fid & 31;
            int m  = mt * 16 + (lf >> 2);
            int k  = kc * 8 + (lf & 3);
            unsigned r0 = f2tf32(Xb[m * 64 + k]);
            unsigned r1 = f2tf32(Xb[(m + 8) * 64 + k]);
            unsigned r2 = f2tf32(Xb[m * 64 + k + 4]);
            unsigned r3 = f2tf32(Xb[(m + 8) * 64 + k + 4]);
            *(uint4*)(xf + fid * 4) = make_uint4(r0, r1, r2, r3);
        }
    }
    __syncthreads();

    // ---- phase A: [32x64]@[64x256] via tf32 mma, W frags pre-converted ----
    {
        const int msel = warp >> 1;
        const int hh   = warp & 1;

        float acc[2][4][4];
        #pragma unroll
        for (int mt = 0; mt < 2; mt++)
            #pragma unroll
            for (int nt = 0; nt < 4; nt++)
                #pragma unroll
                for (int r = 0; r < 4; r++) acc[mt][nt][r] = 0.f;

        const uint4* xf = (const uint4*)xfrag;
        #pragma unroll
        for (int kc = 0; kc < 8; kc++) {
            uint4 A0 = xf[(kc * 2 + 0) * 32 + lane];
            uint4 A1 = xf[(kc * 2 + 1) * 32 + lane];
            uint4 B0 = g_wtab[((warp * 8 + kc) * 2 + 0) * 32 + lane];
            uint4 B1 = g_wtab[((warp * 8 + kc) * 2 + 1) * 32 + lane];
            const unsigned* b0p = &B0.x;
            const unsigned* b1p = &B1.x;
            #pragma unroll
            for (int nt = 0; nt < 4; nt++) {
                mma_tf32(acc[0][nt], A0, b0p[nt], b1p[nt]);
                mma_tf32(acc[1][nt], A1, b0p[nt], b1p[nt]);
            }
        }

        // epilogue: split into interleaved bf16 (hi,lo) uint2 arrays
        #pragma unroll
        for (int mt = 0; mt < 2; mt++) {
            const int m0 = mt * 16 + lq;
            #pragma unroll
            for (int nt = 0; nt < 4; nt++) {
                const float c0 = acc[mt][nt][0], c1 = acc[mt][nt][1];
                const float c2 = acc[mt][nt][2], c3 = acc[mt][nt][3];
                const int cw = nt * 8 + lr * 2;
                if (msel == 0) {                   // Q: rows f, a-pair word cw>>1
                    float l0, l1, l2, l3;
                    unsigned h01 = bf2_hi(c0, c1, l0, l1);
                    unsigned h23 = bf2_hi(c2, c3, l2, l3);
                    q2a[(hh*32 + m0    )*20 + nt*4 + lr] = make_uint2(h01, bf2(l0, l1));
                    q2a[(hh*32 + m0 + 8)*20 + nt*4 + lr] = make_uint2(h23, bf2(l2, l3));
                } else if (msel == 1) {            // K: rows g, a-pair word
                    float l0, l1, l2, l3;
                    unsigned h01 = bf2_hi(c0, c1, l0, l1);
                    unsigned h23 = bf2_hi(c2, c3, l2, l3);
                    k2a[(hh*32 + m0    )*20 + nt*4 + lr] = make_uint2(h01, bf2(l0, l1));
                    k2a[(hh*32 + m0 + 8)*20 + nt*4 + lr] = make_uint2(h23, bf2(l2, l3));
                } else if (msel == 2) {            // V -> transposed vt2[e][g-pair]
                    // value c at (e,g): word w=g>>1; bf16 slot 4*(e*20+w)+ (g&1) hi, +2+(g&1) lo
                    __nv_bfloat16* vb = (__nv_bfloat16*)vt2;
                    #pragma unroll
                    for (int j = 0; j < 4; j++) {
                        const float cv = (j==0)?c0:(j==1)?c1:(j==2)?c2:c3;
                        const int e = hh*32 + cw + (j & 1);
                        const int g = m0 + ((j >> 1) << 3);
                        __nv_bfloat16 hv = __float2bfloat16_rn(cv);
                        const int base = 4 * (e * 20 + (g >> 1)) + (g & 1);
                        vb[base]     = hv;
                        vb[base + 2] = __float2bfloat16_rn(cv - __bfloat162float(hv));
                    }
                } else {                           // Res -> res[f][e] f32
                    int e = (hh<<5) + cw;
                    *(float2*)(res + m0 * 68 + e)       = make_float2(c0, c1);
                    *(float2*)(res + (m0 + 8) * 68 + e) = make_float2(c2, c3);
                }
            }
        }
    }
    __syncthreads();

    // ---- phase B+C: scores via 3-term bf16 m16n8k16 + softmax ----
    // Warps 0-3: h = warp>>1, f-half = warp&1 -> M16(f) x N32(g) x K32(a)
    if (warp < 4) {
        const int h  = warp >> 1;
        const int f0 = (warp & 1) * 16;
        const uint2* qh2 = q2a + h * 640;
        const uint2* kh2 = k2a + h * 640;

        float acc[4][4];
        #pragma unroll
        for (int nt = 0; nt < 4; nt++)
            #pragma unroll
            for (int r = 0; r < 4; r++) acc[nt][r] = 0.f;

        #pragma unroll
        for (int kt = 0; kt < 2; kt++) {
            const int wo = kt * 8 + lr;
            uint2 p0 = qh2[(f0 + lq    )*20 + wo];
            uint2 p1 = qh2[(f0 + lq + 8)*20 + wo];
            uint2 p2 = qh2[(f0 + lq    )*20 + wo + 4];
            uint2 p3 = qh2[(f0 + lq + 8)*20 + wo + 4];
            uint4 Ah = make_uint4(p0.x, p1.x, p2.x, p3.x);
            uint4 Al = make_uint4(p0.y, p1.y, p2.y, p3.y);
            #pragma unroll
            for (int nt = 0; nt < 4; nt++) {
                const int gr = nt * 8 + lq;
                uint2 b0 = kh2[gr*20 + wo];
                uint2 b1 = kh2[gr*20 + wo + 4];
                mma_bf16(acc[nt], Ah, b0.x, b1.x);
                mma_bf16(acc[nt], Ah, b0.y, b1.y);
                mma_bf16(acc[nt], Al, b0.x, b1.x);
            }
        }

        // softmax in fragment domain: rows f0+lq / f0+lq+8 span the lane-quad
        const unsigned qm = 0xFu << (lane & 28);
        float mA = fmaxf(fmaxf(acc[0][0], acc[0][1]), fmaxf(acc[1][0], acc[1][1]));
        mA = fmaxf(mA, fmaxf(fmaxf(acc[2][0], acc[2][1]), fmaxf(acc[3][0], acc[3][1])));
        float mB = fmaxf(fmaxf(acc[0][2], acc[0][3]), fmaxf(acc[1][2], acc[1][3]));
        mB = fmaxf(mB, fmaxf(fmaxf(acc[2][2], acc[2][3]), fmaxf(acc[3][2], acc[3][3])));
        #pragma unroll
        for (int o = 1; o < 4; o <<= 1) {
            mA = fmaxf(mA, __shfl_xor_sync(qm, mA, o));
            mB = fmaxf(mB, __shfl_xor_sync(qm, mB, o));
        }
        float eA[4][2], eB[4][2], sA = 0.f, sB = 0.f;
        #pragma unroll
        for (int nt = 0; nt < 4; nt++) {
            eA[nt][0] = __expf(acc[nt][0] - mA); eA[nt][1] = __expf(acc[nt][1] - mA);
            eB[nt][0] = __expf(acc[nt][2] - mB); eB[nt][1] = __expf(acc[nt][3] - mB);
            sA += eA[nt][0] + eA[nt][1];
            sB += eB[nt][0] + eB[nt][1];
        }
        #pragma unroll
        for (int o = 1; o < 4; o <<= 1) {
            sA += __shfl_xor_sync(qm, sA, o);
            sB += __shfl_xor_sync(qm, sB, o);
        }
        float rA = __fdividef(1.f, sA), rB = __fdividef(1.f, sB);

        // store attn as interleaved (hi,lo) uint2, g-pair word nt*4+lr
        uint2* ah2 = at2 + h * 640;
        #pragma unroll
        for (int nt = 0; nt < 4; nt++) {
            float v0 = eA[nt][0]*rA, v1 = eA[nt][1]*rA;   // row f0+lq
            float w0 = eB[nt][0]*rB, w1 = eB[nt][1]*rB;   // row f0+lq+8
            float l0, l1, l2, l3;
            unsigned hA = bf2_hi(v0, v1, l0, l1);
            unsigned hB = bf2_hi(w0, w1, l2, l3);
            ah2[(f0 + lq    )*20 + nt*4 + lr] = make_uint2(hA, bf2(l0, l1));
            ah2[(f0 + lq + 8)*20 + nt*4 + lr] = make_uint2(hB, bf2(l2, l3));
        }
    }
    __syncthreads();

    // ---- phase D: out = attn @ V + res, relu (3-term bf16, 8 warps) ----
    {
        const int h   = warp >> 2;
        const int f0  = ((warp >> 1) & 1) * 16;
        const int e0h = (warp & 1) * 16;
        const uint2* ah2 = at2 + h * 640;
        const uint2* vh2 = vt2 + h * 640;

        float acc[2][4];
        #pragma unroll
        for (int nt = 0; nt < 2; nt++)
            #pragma unroll
            for (int r = 0; r < 4; r++) acc[nt][r] = 0.f;

        #pragma unroll
        for (int kt = 0; kt < 2; kt++) {
            const int wo = kt * 8 + lr;
            uint2 p0 = ah2[(f0 + lq    )*20 + wo];
            uint2 p1 = ah2[(f0 + lq + 8)*20 + wo];
            uint2 p2 = ah2[(f0 + lq    )*20 + wo + 4];
            uint2 p3 = ah2[(f0 + lq + 8)*20 + wo + 4];
            uint4 Ah = make_uint4(p0.x, p1.x, p2.x, p3.x);
            uint4 Al = make_uint4(p0.y, p1.y, p2.y, p3.y);
            #pragma unroll
            for (int nt = 0; nt < 2; nt++) {
                const int er = e0h + nt * 8 + lq;
                uint2 b0 = vh2[er*20 + wo];
                uint2 b1 = vh2[er*20 + wo + 4];
                mma_bf16(acc[nt], Ah, b0.x, b1.x);
                mma_bf16(acc[nt], Ah, b0.y, b1.y);
                mma_bf16(acc[nt], Al, b0.x, b1.x);
            }
        }

        // epilogue: + res, relu, store
        #pragma unroll
        for (int nt = 0; nt < 2; nt++) {
            const int eg = (h << 5) + e0h + nt * 8 + 2 * lr;
            const int fA = f0 + lq, fB = f0 + lq + 8;
            float2 r0 = *(const float2*)(res + fA * 68 + eg);
            float2 r1 = *(const float2*)(res + fB * 68 + eg);
            float o0 = fmaxf(acc[nt][0] + r0.x, 0.f);
            float o1 = fmaxf(acc[nt][1] + r0.y, 0.f);
            float o2 = fmaxf(acc[nt][2] + r1.x, 0.f);
            float o3 = fmaxf(acc[nt][3] + r1.y, 0.f);
            *(float2*)(Out + b * 2048 + fA * 64 + eg) = make_float2(o0, o1);
            *(float2*)(Out + b * 2048 + fB * 64 + eg) = make_float2(o2, o3);
        }
    }
}

extern "C" void kernel_launch(void* const* d_in, const int* in_sizes, int n_in,
                              void* d_out, int out_size)
{
    const float* X  = (const float*)d_in[0];
    const float* Wq = (const float*)d_in[1];
    const float* Wk = (const float*)d_in[2];
    const float* Wv = (const float*)d_in[3];
    const float* Wr = (const float*)d_in[4];
    float* Out = (float*)d_out;

    const int nb = in_sizes[0] / 2048;          // 16384 batches
    const size_t smem = 12416 * sizeof(float);  // 49664 B

    wtab_init<<<8, 256>>>(Wq, Wk, Wv, Wr);

    cudaFuncSetAttribute(interact_kernel,
                         cudaFuncAttributeMaxDynamicSharedMemorySize, (int)smem);
    interact_kernel<<<nb, 256, smem>>>(X, Out);
}